// round 3
// baseline (speedup 1.0000x reference)
#include <cuda_runtime.h>
#include <cuda_bf16.h>
#include <cstdint>

#define DI __device__ __forceinline__

// ---------------- problem sizes ----------------
constexpr int Bc = 32, Sc = 256, Tc = 64, T1c = 65;
constexpr int Hc = 512, Ec = 300, Vc = 32000, H3c = 1536;
constexpr int ROWS = Bc * Tc;            // 2048

// ---------------- device scratch ----------------
__device__ float g_x    [ROWS * Ec];
__device__ float g_gi   [ROWS * H3c];
__device__ float g_hta  [Hc * Bc];       // transposed hidden [k][b]
__device__ float g_htb  [Hc * Bc];
__device__ float g_hseq0[ROWS * Hc];
__device__ float g_hseq1[ROWS * Hc];
__device__ float g_proj [Bc * Sc * Hc];
__device__ float g_scores[ROWS * Sc];
__device__ float g_encT [Bc * 2 * Hc * Sc];   // [b][d][s]
__device__ float g_cat  [ROWS * H3c];
__device__ float g_o    [ROWS * H3c];

// ---------------- helpers ----------------
DI void mma16(float c[4], const uint32_t a[4], const uint32_t b[2]) {
    asm volatile(
        "mma.sync.aligned.m16n8k16.row.col.f32.bf16.bf16.f32 "
        "{%0,%1,%2,%3}, {%4,%5,%6,%7}, {%8,%9}, {%0,%1,%2,%3};"
        : "+f"(c[0]), "+f"(c[1]), "+f"(c[2]), "+f"(c[3])
        : "r"(a[0]), "r"(a[1]), "r"(a[2]), "r"(a[3]), "r"(b[0]), "r"(b[1]));
}

// split two floats into packed bf16x2 (hi) and packed bf16x2 (lo), low half = x
DI void split2(float x, float y, uint32_t& hi, uint32_t& lo) {
    __nv_bfloat162 h = __floats2bfloat162_rn(x, y);
    float hx = __bfloat162float(__low2bfloat16(h));
    float hy = __bfloat162float(__high2bfloat16(h));
    __nv_bfloat162 l = __floats2bfloat162_rn(x - hx, y - hy);
    hi = *reinterpret_cast<uint32_t*>(&h);
    lo = *reinterpret_cast<uint32_t*>(&l);
}

// ---------------- embed gather + relu ----------------
__global__ void embed_relu_kernel(const int* __restrict__ words,
                                  const float* __restrict__ embed) {
    int row = blockIdx.x;            // b*64 + t
    int b = row >> 6, t = row & 63;
    int w = words[b * T1c + t];
    const float* e = embed + (long long)w * Ec;
    float* x = g_x + (long long)row * Ec;
    for (int i = threadIdx.x; i < Ec; i += blockDim.x)
        x[i] = fmaxf(e[i], 0.f);
}

// ---------------- h0 (transposed) ----------------
__global__ void h0t_kernel(const float* __restrict__ ehid, int layer) {
    int i = blockIdx.x * blockDim.x + threadIdx.x;   // over 32*512
    if (i < Bc * Hc) {
        int b = i >> 9, j = i & 511;
        g_hta[j * Bc + b] = ehid[layer * Bc * Hc + i] + ehid[(layer + 2) * Bc * Hc + i];
    }
}

// ---------------- encoder_output transpose [b][s][d] -> [b][d][s] -------
__global__ void transpose_enc(const float* __restrict__ enc) {
    __shared__ float t[32][33];
    int b = blockIdx.z;
    int d0 = blockIdx.x * 32, s0 = blockIdx.y * 32;
    int tx = threadIdx.x, ty = threadIdx.y;
#pragma unroll
    for (int i = 0; i < 4; i++)
        t[ty + 8 * i][tx] =
            enc[((long long)b * Sc + s0 + ty + 8 * i) * (2 * Hc) + d0 + tx];
    __syncthreads();
#pragma unroll
    for (int i = 0; i < 4; i++)
        g_encT[((long long)b * (2 * Hc) + d0 + ty + 8 * i) * Sc + s0 + tx] =
            t[tx][ty + 8 * i];
}

// ---------------- fp32 SIMT GEMM: C = A @ W^T + bias ----------------
__global__ void __launch_bounds__(256)
simt_gemm(const float* __restrict__ A, const float* __restrict__ W,
          const float* __restrict__ bias, float* __restrict__ C,
          int M, int N, int K) {
    __shared__ float As[16 * 68];
    __shared__ float Bs[16 * 68];
    int tid = threadIdx.x;
    int tx = tid & 15, ty = tid >> 4;
    int m0 = blockIdx.y * 64, n0 = blockIdx.x * 64;
    float c[4][4] = {};
    int kt_count = (K + 15) / 16;
    for (int kt = 0; kt < kt_count; kt++) {
        int k0 = kt * 16;
        __syncthreads();
#pragma unroll
        for (int e = tid; e < 1024; e += 256) {
            int r = e >> 4, k = e & 15;
            As[k * 68 + r] = (k0 + k < K) ? A[(long long)(m0 + r) * K + k0 + k] : 0.f;
            Bs[k * 68 + r] = (k0 + k < K) ? W[(long long)(n0 + r) * K + k0 + k] : 0.f;
        }
        __syncthreads();
#pragma unroll
        for (int k = 0; k < 16; k++) {
            float4 a = *(const float4*)&As[k * 68 + ty * 4];
            float4 b = *(const float4*)&Bs[k * 68 + tx * 4];
            float av[4] = {a.x, a.y, a.z, a.w};
            float bv[4] = {b.x, b.y, b.z, b.w};
#pragma unroll
            for (int i = 0; i < 4; i++)
#pragma unroll
                for (int j = 0; j < 4; j++)
                    c[i][j] += av[i] * bv[j];
        }
    }
#pragma unroll
    for (int i = 0; i < 4; i++)
#pragma unroll
        for (int j = 0; j < 4; j++) {
            int row = m0 + ty * 4 + i, col = n0 + tx * 4 + j;
            C[(long long)row * N + col] = c[i][j] + bias[col];
        }
}

// ---------------- fused GRU step ----------------
__global__ void __launch_bounds__(256)
gru_step_kernel(const float* __restrict__ Whh, const float* __restrict__ bhh,
                int t, int layer) {
    __shared__ float sp[3][4][32];
    const float* hin = (t & 1) ? g_htb : g_hta;
    float* hout      = (t & 1) ? g_hta : g_htb;
    float* hseq      = layer ? g_hseq1 : g_hseq0;

    int tid = threadIdx.x;
    int b  = tid & 31;
    int jl = (tid >> 5) & 3;
    int kh = tid >> 7;
    int j  = blockIdx.x * 4 + jl;

    const float* wr = Whh + (long long)j * Hc;
    const float* wz = wr + (long long)Hc * Hc;
    const float* wn = wr + (long long)2 * Hc * Hc;

    float ar = 0.f, az = 0.f, an = 0.f;
    int k0 = kh * 256;
#pragma unroll 4
    for (int k = k0; k < k0 + 256; k += 4) {
        float4 r4 = *(const float4*)(wr + k);
        float4 z4 = *(const float4*)(wz + k);
        float4 n4 = *(const float4*)(wn + k);
        float h0v = hin[(k + 0) * Bc + b];
        float h1v = hin[(k + 1) * Bc + b];
        float h2v = hin[(k + 2) * Bc + b];
        float h3v = hin[(k + 3) * Bc + b];
        ar += r4.x * h0v + r4.y * h1v + r4.z * h2v + r4.w * h3v;
        az += z4.x * h0v + z4.y * h1v + z4.z * h2v + z4.w * h3v;
        an += n4.x * h0v + n4.y * h1v + n4.z * h2v + n4.w * h3v;
    }
    if (kh) {
        sp[0][jl][b] = ar; sp[1][jl][b] = az; sp[2][jl][b] = an;
    }
    __syncthreads();
    if (!kh) {
        ar += sp[0][jl][b]; az += sp[1][jl][b]; an += sp[2][jl][b];
        int row = b * Tc + t;
        const float* g = g_gi + (long long)row * H3c;
        float grv = g[j] + ar + bhh[j];
        float gzv = g[j + Hc] + az + bhh[j + Hc];
        float ghn = an + bhh[j + 2 * Hc];
        float r = 1.f / (1.f + expf(-grv));
        float z = 1.f / (1.f + expf(-gzv));
        float n = tanhf(g[j + 2 * Hc] + r * ghn);
        float hold = hin[j * Bc + b];
        float hnew = (1.f - z) * n + z * hold;
        hout[j * Bc + b] = hnew;
        hseq[(long long)row * Hc + j] = hnew;
        if (layer) g_cat[(long long)row * H3c + j] = hnew;
    }
}

// ---------------- softmax over last dim (256) ----------------
__global__ void softmax_kernel() {
    int row = blockIdx.x, tid = threadIdx.x;
    __shared__ float sm_[8], ss_[8];
    float v = g_scores[(long long)row * Sc + tid];
    float m = v;
#pragma unroll
    for (int o = 16; o; o >>= 1) m = fmaxf(m, __shfl_xor_sync(~0u, m, o));
    if ((tid & 31) == 0) sm_[tid >> 5] = m;
    __syncthreads();
    float mm = sm_[0];
#pragma unroll
    for (int i = 1; i < 8; i++) mm = fmaxf(mm, sm_[i]);
    float e = expf(v - mm);
    float s = e;
#pragma unroll
    for (int o = 16; o; o >>= 1) s += __shfl_xor_sync(~0u, s, o);
    if ((tid & 31) == 0) ss_[tid >> 5] = s;
    __syncthreads();
    float tot = 0.f;
#pragma unroll
    for (int i = 0; i < 8; i++) tot += ss_[i];
    g_scores[(long long)row * Sc + tid] = e / tot;
}

// ---------------- bf16x3 split tensor-core GEMM ----------------
// C = A @ B^T (+bias)(+relu). A [M][lda] fp32, B [N][K] fp32, C [M][ldc] fp32.
// BM=BN=128, BK=32. Each fp32 split into bf16 hi+lo; 3 MMAs per fragment pair.
// smem planes: packed bf16x2 words, row stride 20 u32 (conflict-free frag LDS).
constexpr int PLN = 128 * 20;                  // u32 per plane
constexpr int BF16_SMEM = 8 * PLN * 4;         // 2 stages x (Ahi,Alo,Bhi,Blo)

template <bool RELU>
__global__ void __launch_bounds__(256, 1)
bf16x3_gemm(const float* __restrict__ A, const float* __restrict__ Bw,
            const float* __restrict__ bias, float* __restrict__ C,
            int M, int N, int K, int lda, int ldc,
            long long sA, long long sB, long long sC) {
    extern __shared__ uint32_t smu[];

    A  += (long long)blockIdx.z * sA;
    Bw += (long long)blockIdx.z * sB;
    C  += (long long)blockIdx.z * sC;

    int m0 = blockIdx.x * 128, n0 = blockIdx.y * 128;
    int tid = threadIdx.x;
    int lane = tid & 31, wid = tid >> 5;
    int wm = wid & 1, wn = wid >> 1;        // warp tile 64x32
    int lr = lane >> 2, lc = lane & 3;

    float c[4][4][4] = {};

    int ldr  = tid >> 3;             // 0..31 row base
    int ldc4 = (tid & 7) * 4;        // col within 32-wide K block
    int pcol = ldc4 >> 1;            // u32 pair column (even)

    float4 av[4], bv[4];
    auto gload = [&](int k0g) {
#pragma unroll
        for (int it = 0; it < 4; it++) {
            int r = ldr + it * 32;
            int gm = m0 + r;
            av[it] = (gm < M) ? *(const float4*)(A + (long long)gm * lda + k0g + ldc4)
                              : make_float4(0.f, 0.f, 0.f, 0.f);
            bv[it] = *(const float4*)(Bw + (long long)(n0 + r) * K + k0g + ldc4);
        }
    };
    auto sts = [&](int stage) {
        uint32_t* Ahi = smu + stage * 4 * PLN;
        uint32_t* Alo = Ahi + PLN;
        uint32_t* Bhi = Alo + PLN;
        uint32_t* Blo = Bhi + PLN;
#pragma unroll
        for (int it = 0; it < 4; it++) {
            int r = ldr + it * 32;
            uint32_t h0, l0, h1, l1;
            split2(av[it].x, av[it].y, h0, l0);
            split2(av[it].z, av[it].w, h1, l1);
            *(uint2*)&Ahi[r * 20 + pcol] = make_uint2(h0, h1);
            *(uint2*)&Alo[r * 20 + pcol] = make_uint2(l0, l1);
            split2(bv[it].x, bv[it].y, h0, l0);
            split2(bv[it].z, bv[it].w, h1, l1);
            *(uint2*)&Bhi[r * 20 + pcol] = make_uint2(h0, h1);
            *(uint2*)&Blo[r * 20 + pcol] = make_uint2(l0, l1);
        }
    };

    int kt_count = K >> 5;
    gload(0);
    sts(0);
    for (int kt = 0; kt < kt_count; kt++) {
        __syncthreads();
        if (kt + 1 < kt_count) gload((kt + 1) << 5);
        const uint32_t* Ahi = smu + (kt & 1) * 4 * PLN;
        const uint32_t* Alo = Ahi + PLN;
        const uint32_t* Bhi = Alo + PLN;
        const uint32_t* Blo = Bhi + PLN;
#pragma unroll
        for (int ks = 0; ks < 2; ks++) {          // two k16 steps per BK=32
            int kp = ks * 8;                      // pair-column base
            uint32_t ah[4][4], al[4][4], bh[4][2], bl[4][2];
#pragma unroll
            for (int mi = 0; mi < 4; mi++) {
                int rb = wm * 64 + mi * 16;
                ah[mi][0] = Ahi[(rb + lr) * 20 + kp + lc];
                ah[mi][1] = Ahi[(rb + 8 + lr) * 20 + kp + lc];
                ah[mi][2] = Ahi[(rb + lr) * 20 + kp + lc + 4];
                ah[mi][3] = Ahi[(rb + 8 + lr) * 20 + kp + lc + 4];
                al[mi][0] = Alo[(rb + lr) * 20 + kp + lc];
                al[mi][1] = Alo[(rb + 8 + lr) * 20 + kp + lc];
                al[mi][2] = Alo[(rb + lr) * 20 + kp + lc + 4];
                al[mi][3] = Alo[(rb + 8 + lr) * 20 + kp + lc + 4];
            }
#pragma unroll
            for (int ni = 0; ni < 4; ni++) {
                int nb = wn * 32 + ni * 8;
                bh[ni][0] = Bhi[(nb + lr) * 20 + kp + lc];
                bh[ni][1] = Bhi[(nb + lr) * 20 + kp + lc + 4];
                bl[ni][0] = Blo[(nb + lr) * 20 + kp + lc];
                bl[ni][1] = Blo[(nb + lr) * 20 + kp + lc + 4];
            }
#pragma unroll
            for (int mi = 0; mi < 4; mi++)
#pragma unroll
                for (int ni = 0; ni < 4; ni++) {
                    mma16(c[mi][ni], ah[mi], bh[ni]);
                    mma16(c[mi][ni], ah[mi], bl[ni]);
                    mma16(c[mi][ni], al[mi], bh[ni]);
                }
        }
        if (kt + 1 < kt_count) sts((kt + 1) & 1);
    }

    // epilogue
#pragma unroll
    for (int mi = 0; mi < 4; mi++) {
#pragma unroll
        for (int ni = 0; ni < 4; ni++) {
            int row = m0 + wm * 64 + mi * 16 + lr;
            int col = n0 + wn * 32 + ni * 8 + lc * 2;
            float b0 = bias ? bias[col] : 0.f;
            float b1 = bias ? bias[col + 1] : 0.f;
            float v0 = c[mi][ni][0] + b0, v1 = c[mi][ni][1] + b1;
            float v2 = c[mi][ni][2] + b0, v3 = c[mi][ni][3] + b1;
            if (RELU) {
                v0 = fmaxf(v0, 0.f); v1 = fmaxf(v1, 0.f);
                v2 = fmaxf(v2, 0.f); v3 = fmaxf(v3, 0.f);
            }
            if (row < M)
                *(float2*)(C + (long long)row * ldc + col) = make_float2(v0, v1);
            if (row + 8 < M)
                *(float2*)(C + (long long)(row + 8) * ldc + col) = make_float2(v2, v3);
        }
    }
}

// ---------------- host launch ----------------
extern "C" void kernel_launch(void* const* d_in, const int* in_sizes, int n_in,
                              void* d_out, int out_size) {
    (void)in_sizes; (void)n_in; (void)out_size;
    const float* enc    = (const float*)d_in[0];
    const float* ehid   = (const float*)d_in[1];
    const int*   words  = (const int*)d_in[2];
    const float* embed  = (const float*)d_in[3];
    const float* Wih0   = (const float*)d_in[4];
    const float* Whh0   = (const float*)d_in[5];
    const float* bih0   = (const float*)d_in[6];
    const float* bhh0   = (const float*)d_in[7];
    const float* Wih1   = (const float*)d_in[8];
    const float* Whh1   = (const float*)d_in[9];
    const float* bih1   = (const float*)d_in[10];
    const float* bhh1   = (const float*)d_in[11];
    const float* attn_W = (const float*)d_in[12];
    const float* attn_b = (const float*)d_in[13];
    const float* aw_W   = (const float*)d_in[14];
    const float* aw_b   = (const float*)d_in[15];
    const float* out_W  = (const float*)d_in[16];
    const float* out_b  = (const float*)d_in[17];
    float* out = (float*)d_out;

    float *p_x, *p_gi, *p_h0, *p_h1, *p_proj, *p_sc, *p_encT, *p_cat, *p_o;
    cudaGetSymbolAddress((void**)&p_x,    g_x);
    cudaGetSymbolAddress((void**)&p_gi,   g_gi);
    cudaGetSymbolAddress((void**)&p_h0,   g_hseq0);
    cudaGetSymbolAddress((void**)&p_h1,   g_hseq1);
    cudaGetSymbolAddress((void**)&p_proj, g_proj);
    cudaGetSymbolAddress((void**)&p_sc,   g_scores);
    cudaGetSymbolAddress((void**)&p_encT, g_encT);
    cudaGetSymbolAddress((void**)&p_cat,  g_cat);
    cudaGetSymbolAddress((void**)&p_o,    g_o);

    cudaFuncSetAttribute(bf16x3_gemm<false>,
                         cudaFuncAttributeMaxDynamicSharedMemorySize, BF16_SMEM);
    cudaFuncSetAttribute(bf16x3_gemm<true>,
                         cudaFuncAttributeMaxDynamicSharedMemorySize, BF16_SMEM);

    // independent prep
    embed_relu_kernel<<<ROWS, 128>>>(words, embed);
    transpose_enc<<<dim3(32, 8, 32), dim3(32, 8)>>>(enc);

    // ---- layer 0 ----
    h0t_kernel<<<64, 256>>>(ehid, 0);
    simt_gemm<<<dim3(H3c / 64, ROWS / 64), 256>>>(p_x, Wih0, bih0, p_gi,
                                                  ROWS, H3c, Ec);
    for (int t = 0; t < Tc; t++)
        gru_step_kernel<<<128, 256>>>(Whh0, bhh0, t, 0);

    // ---- layer 1 ----
    h0t_kernel<<<64, 256>>>(ehid, 1);
    simt_gemm<<<dim3(H3c / 64, ROWS / 64), 256>>>(p_h0, Wih1, bih1, p_gi,
                                                  ROWS, H3c, Hc);
    for (int t = 0; t < Tc; t++)
        gru_step_kernel<<<128, 256>>>(Whh1, bhh1, t, 1);

    // ---- attention ----
    // proj = enc @ attn_W^T + attn_b : M=8192 N=512 K=1024
    bf16x3_gemm<false><<<dim3(64, 4, 1), 256, BF16_SMEM>>>(
        enc, attn_W, attn_b, p_proj, Bc * Sc, Hc, 2 * Hc, 2 * Hc, Hc, 0, 0, 0);
    // scores[b] = h[b] @ proj[b]^T : M=64 N=256 K=512, batched 32
    bf16x3_gemm<false><<<dim3(1, 2, 32), 256, BF16_SMEM>>>(
        p_h1, p_proj, nullptr, p_sc, Tc, Sc, Hc, Hc, Sc,
        (long long)Tc * Hc, (long long)Sc * Hc, (long long)Tc * Sc);
    softmax_kernel<<<ROWS, 256>>>();
    // ctx[b] = attn[b] @ encT[b]^T : M=64 N=1024 K=256
    bf16x3_gemm<false><<<dim3(1, 8, 32), 256, BF16_SMEM>>>(
        p_sc, p_encT, nullptr, p_cat + Hc, Tc, 2 * Hc, Sc, Sc, H3c,
        (long long)Tc * Sc, (long long)2 * Hc * Sc, (long long)Tc * H3c);

    // ---- output head ----
    bf16x3_gemm<true><<<dim3(16, 12, 1), 256, BF16_SMEM>>>(
        p_cat, aw_W, aw_b, p_o, ROWS, H3c, H3c, H3c, H3c, 0, 0, 0);
    bf16x3_gemm<false><<<dim3(16, 250, 1), 256, BF16_SMEM>>>(
        p_o, out_W, out_b, out, ROWS, Vc, H3c, H3c, Vc, 0, 0, 0);
}

// round 4
// speedup vs baseline: 1.0033x; 1.0033x over previous
#include <cuda_runtime.h>
#include <cuda_bf16.h>
#include <cstdint>

#define DI __device__ __forceinline__

// ---------------- problem sizes ----------------
constexpr int Bc = 32, Sc = 256, Tc = 64, T1c = 65;
constexpr int Hc = 512, Ec = 300, Vc = 32000, H3c = 1536;
constexpr int ROWS = Bc * Tc;            // 2048

// ---------------- fp32 scratch ----------------
__device__ __align__(16) float g_x    [ROWS * Ec];
__device__ __align__(16) float g_gi   [ROWS * H3c];
__device__ __align__(16) float g_hta  [Hc * Bc];
__device__ __align__(16) float g_htb  [Hc * Bc];
__device__ __align__(16) float g_hseq0[ROWS * Hc];
__device__ __align__(16) float g_scores[ROWS * Sc];

// ---------------- bf16 hi/lo planes ----------------
#define PLANES_DECL(name, n) \
    __device__ __align__(16) __nv_bfloat16 name##_hi[n]; \
    __device__ __align__(16) __nv_bfloat16 name##_lo[n];

PLANES_DECL(g_enc,   Bc * Sc * 2 * Hc)     // encoder_output
PLANES_DECL(g_attnW, Hc * 2 * Hc)
PLANES_DECL(g_proj,  Bc * Sc * Hc)
PLANES_DECL(g_encT,  Bc * 2 * Hc * Sc)
PLANES_DECL(g_attn,  ROWS * Sc)
PLANES_DECL(g_cat,   ROWS * H3c)
PLANES_DECL(g_awW,   H3c * H3c)
PLANES_DECL(g_o,     ROWS * H3c)
PLANES_DECL(g_outW,  Vc * H3c)

// ---------------- helpers ----------------
DI void mma16(float c[4], const uint32_t a[4], const uint32_t b[2]) {
    asm volatile(
        "mma.sync.aligned.m16n8k16.row.col.f32.bf16.bf16.f32 "
        "{%0,%1,%2,%3}, {%4,%5,%6,%7}, {%8,%9}, {%0,%1,%2,%3};"
        : "+f"(c[0]), "+f"(c[1]), "+f"(c[2]), "+f"(c[3])
        : "r"(a[0]), "r"(a[1]), "r"(a[2]), "r"(a[3]), "r"(b[0]), "r"(b[1]));
}
#define LDSM4(R, addr) \
    asm volatile("ldmatrix.sync.aligned.m8n8.x4.shared.b16 {%0,%1,%2,%3}, [%4];" \
                 : "=r"((R)[0]), "=r"((R)[1]), "=r"((R)[2]), "=r"((R)[3]) : "r"(addr))

DI void cpa16(uint32_t dst, const void* src, bool ok) {
    int sz = ok ? 16 : 0;
    asm volatile("cp.async.cg.shared.global [%0], [%1], 16, %2;\n"
                 :: "r"(dst), "l"(src), "r"(sz));
}
DI void cp_commit() { asm volatile("cp.async.commit_group;\n"); }
DI void cp_wait1()  { asm volatile("cp.async.wait_group 1;\n"); }

DI void splits(float v, __nv_bfloat16& h, __nv_bfloat16& l) {
    h = __float2bfloat16(v);
    l = __float2bfloat16(v - __bfloat162float(h));
}

// ---------------- fp32 -> bf16 hi/lo plane split ----------------
__global__ void split_kernel(const float* __restrict__ s,
                             __nv_bfloat16* __restrict__ hi,
                             __nv_bfloat16* __restrict__ lo, int n4) {
    int i = blockIdx.x * blockDim.x + threadIdx.x;
    if (i >= n4) return;
    float4 v = ((const float4*)s)[i];
    __nv_bfloat162 h0 = __floats2bfloat162_rn(v.x, v.y);
    __nv_bfloat162 h1 = __floats2bfloat162_rn(v.z, v.w);
    __nv_bfloat162 l0 = __floats2bfloat162_rn(v.x - __bfloat162float(__low2bfloat16(h0)),
                                              v.y - __bfloat162float(__high2bfloat16(h0)));
    __nv_bfloat162 l1 = __floats2bfloat162_rn(v.z - __bfloat162float(__low2bfloat16(h1)),
                                              v.w - __bfloat162float(__high2bfloat16(h1)));
    ((__nv_bfloat162*)hi)[2 * i] = h0;
    ((__nv_bfloat162*)hi)[2 * i + 1] = h1;
    ((__nv_bfloat162*)lo)[2 * i] = l0;
    ((__nv_bfloat162*)lo)[2 * i + 1] = l1;
}

// ---------------- embed gather + relu ----------------
__global__ void embed_relu_kernel(const int* __restrict__ words,
                                  const float* __restrict__ embed) {
    int row = blockIdx.x;
    int b = row >> 6, t = row & 63;
    int w = words[b * T1c + t];
    const float* e = embed + (long long)w * Ec;
    float* x = g_x + (long long)row * Ec;
    for (int i = threadIdx.x; i < Ec; i += blockDim.x)
        x[i] = fmaxf(e[i], 0.f);
}

// ---------------- h0 (transposed) ----------------
__global__ void h0t_kernel(const float* __restrict__ ehid, int layer) {
    int i = blockIdx.x * blockDim.x + threadIdx.x;
    if (i < Bc * Hc) {
        int b = i >> 9, j = i & 511;
        g_hta[j * Bc + b] = ehid[layer * Bc * Hc + i] + ehid[(layer + 2) * Bc * Hc + i];
    }
}

// ------------- encoder transpose [b][s][d] -> [b][d][s] planes -------------
__global__ void transpose_enc(const float* __restrict__ enc) {
    __shared__ float t[32][33];
    int b = blockIdx.z;
    int d0 = blockIdx.x * 32, s0 = blockIdx.y * 32;
    int tx = threadIdx.x, ty = threadIdx.y;
#pragma unroll
    for (int i = 0; i < 4; i++)
        t[ty + 8 * i][tx] =
            enc[((long long)b * Sc + s0 + ty + 8 * i) * (2 * Hc) + d0 + tx];
    __syncthreads();
#pragma unroll
    for (int i = 0; i < 4; i++) {
        float v = t[tx][ty + 8 * i];
        long long idx = ((long long)b * (2 * Hc) + d0 + ty + 8 * i) * Sc + s0 + tx;
        __nv_bfloat16 h, l; splits(v, h, l);
        g_encT_hi[idx] = h; g_encT_lo[idx] = l;
    }
}

// ---------------- fp32 SIMT GEMM (gi): C = A @ W^T + bias ----------------
__global__ void __launch_bounds__(256)
simt_gemm(const float* __restrict__ A, const float* __restrict__ W,
          const float* __restrict__ bias, float* __restrict__ C,
          int M, int N, int K) {
    __shared__ float As[16 * 68];
    __shared__ float Bs[16 * 68];
    int tid = threadIdx.x;
    int tx = tid & 15, ty = tid >> 4;
    int m0 = blockIdx.y * 64, n0 = blockIdx.x * 64;
    float c[4][4] = {};
    int kt_count = (K + 15) / 16;
    for (int kt = 0; kt < kt_count; kt++) {
        int k0 = kt * 16;
        __syncthreads();
#pragma unroll
        for (int e = tid; e < 1024; e += 256) {
            int r = e >> 4, k = e & 15;
            As[k * 68 + r] = (k0 + k < K) ? A[(long long)(m0 + r) * K + k0 + k] : 0.f;
            Bs[k * 68 + r] = (k0 + k < K) ? W[(long long)(n0 + r) * K + k0 + k] : 0.f;
        }
        __syncthreads();
#pragma unroll
        for (int k = 0; k < 16; k++) {
            float4 a = *(const float4*)&As[k * 68 + ty * 4];
            float4 b = *(const float4*)&Bs[k * 68 + tx * 4];
            float av[4] = {a.x, a.y, a.z, a.w};
            float bv[4] = {b.x, b.y, b.z, b.w};
#pragma unroll
            for (int i = 0; i < 4; i++)
#pragma unroll
                for (int j = 0; j < 4; j++)
                    c[i][j] += av[i] * bv[j];
        }
    }
#pragma unroll
    for (int i = 0; i < 4; i++)
#pragma unroll
        for (int j = 0; j < 4; j++) {
            int row = m0 + ty * 4 + i, col = n0 + tx * 4 + j;
            C[(long long)row * N + col] = c[i][j] + bias[col];
        }
}

// ---------------- fused GRU step ----------------
__global__ void __launch_bounds__(256)
gru_step_kernel(const float* __restrict__ Whh, const float* __restrict__ bhh,
                int t, int layer) {
    __shared__ float sp[3][4][32];
    const float* hin = (t & 1) ? g_htb : g_hta;
    float* hout      = (t & 1) ? g_hta : g_htb;

    int tid = threadIdx.x;
    int b  = tid & 31;
    int jl = (tid >> 5) & 3;
    int kh = tid >> 7;
    int j  = blockIdx.x * 4 + jl;

    const float* wr = Whh + (long long)j * Hc;
    const float* wz = wr + (long long)Hc * Hc;
    const float* wn = wr + (long long)2 * Hc * Hc;

    float ar = 0.f, az = 0.f, an = 0.f;
    int k0 = kh * 256;
#pragma unroll 4
    for (int k = k0; k < k0 + 256; k += 4) {
        float4 r4 = *(const float4*)(wr + k);
        float4 z4 = *(const float4*)(wz + k);
        float4 n4 = *(const float4*)(wn + k);
        float h0v = hin[(k + 0) * Bc + b];
        float h1v = hin[(k + 1) * Bc + b];
        float h2v = hin[(k + 2) * Bc + b];
        float h3v = hin[(k + 3) * Bc + b];
        ar += r4.x * h0v + r4.y * h1v + r4.z * h2v + r4.w * h3v;
        az += z4.x * h0v + z4.y * h1v + z4.z * h2v + z4.w * h3v;
        an += n4.x * h0v + n4.y * h1v + n4.z * h2v + n4.w * h3v;
    }
    if (kh) {
        sp[0][jl][b] = ar; sp[1][jl][b] = az; sp[2][jl][b] = an;
    }
    __syncthreads();
    if (!kh) {
        ar += sp[0][jl][b]; az += sp[1][jl][b]; an += sp[2][jl][b];
        int row = b * Tc + t;
        const float* g = g_gi + (long long)row * H3c;
        float grv = g[j] + ar + bhh[j];
        float gzv = g[j + Hc] + az + bhh[j + Hc];
        float ghn = an + bhh[j + 2 * Hc];
        float r = 1.f / (1.f + expf(-grv));
        float z = 1.f / (1.f + expf(-gzv));
        float n = tanhf(g[j + 2 * Hc] + r * ghn);
        float hold = hin[j * Bc + b];
        float hnew = (1.f - z) * n + z * hold;
        hout[j * Bc + b] = hnew;
        if (layer == 0) {
            g_hseq0[(long long)row * Hc + j] = hnew;
        } else {
            __nv_bfloat16 h, l; splits(hnew, h, l);
            g_cat_hi[(long long)row * H3c + j] = h;
            g_cat_lo[(long long)row * H3c + j] = l;
        }
    }
}

// ---------------- softmax (256 wide) -> attn planes ----------------
__global__ void softmax_kernel() {
    int row = blockIdx.x, tid = threadIdx.x;
    __shared__ float sm_[8], ss_[8];
    float v = g_scores[(long long)row * Sc + tid];
    float m = v;
#pragma unroll
    for (int o = 16; o; o >>= 1) m = fmaxf(m, __shfl_xor_sync(~0u, m, o));
    if ((tid & 31) == 0) sm_[tid >> 5] = m;
    __syncthreads();
    float mm = sm_[0];
#pragma unroll
    for (int i = 1; i < 8; i++) mm = fmaxf(mm, sm_[i]);
    float e = expf(v - mm);
    float s = e;
#pragma unroll
    for (int o = 16; o; o >>= 1) s += __shfl_xor_sync(~0u, s, o);
    if ((tid & 31) == 0) ss_[tid >> 5] = s;
    __syncthreads();
    float tot = 0.f;
#pragma unroll
    for (int i = 0; i < 8; i++) tot += ss_[i];
    float p = e / tot;
    __nv_bfloat16 h, l; splits(p, h, l);
    g_attn_hi[(long long)row * Sc + tid] = h;
    g_attn_lo[(long long)row * Sc + tid] = l;
}

// ======================= bf16x3 pipelined tensor GEMM =======================
// C = A @ B^T (+bias)(+relu). A,B pre-split bf16 hi/lo planes.
// A [M][lda], B [N][K] (ld=K). BM=BN=128, BK=32, 3-stage cp.async, ldmatrix.
// smem per stage: 4 planes x 128 rows x 64B = 32 KB. swizzle: c ^= (r>>1)&3.
constexpr int GSTAGE = 32768;
constexpr int GSMEM  = 3 * GSTAGE;

template <bool RELU, bool PLANES>
__global__ void __launch_bounds__(256, 1)
bfx3_gemm(const __nv_bfloat16* __restrict__ Ahi, const __nv_bfloat16* __restrict__ Alo,
          const __nv_bfloat16* __restrict__ Bhi, const __nv_bfloat16* __restrict__ Blo,
          const float* __restrict__ bias, float* __restrict__ C,
          __nv_bfloat16* __restrict__ Chi, __nv_bfloat16* __restrict__ Clo,
          int M, int N, int K, int lda, int ldc,
          long long sA, long long sB, long long sC) {
    extern __shared__ char smem[];
    uint32_t su = (uint32_t)__cvta_generic_to_shared(smem);

    Ahi += (long long)blockIdx.z * sA;  Alo += (long long)blockIdx.z * sA;
    Bhi += (long long)blockIdx.z * sB;  Blo += (long long)blockIdx.z * sB;
    if (PLANES) { Chi += (long long)blockIdx.z * sC; Clo += (long long)blockIdx.z * sC; }
    else        { C   += (long long)blockIdx.z * sC; }

    const int m0 = blockIdx.x * 128, n0 = blockIdx.y * 128;
    const int tid = threadIdx.x;
    const int lane = tid & 31, wid = tid >> 5;
    const int wm = wid & 1, wn = wid >> 1;       // warp tile 64(m) x 32(n)
    const int lr = lane >> 2, lc = lane & 3;

    float c[4][4][4] = {};

    auto issue_load = [&](int stage, int kt) {
        int kb = kt * 32;
        uint32_t sb = su + stage * GSTAGE;
#pragma unroll
        for (int i = 0; i < 8; i++) {
            int chunkid = tid + 256 * i;
            int plane = chunkid >> 9;
            int w = chunkid & 511;
            int r = w >> 2, cck = w & 3;
            uint32_t dst = sb + plane * 8192 + r * 64 + ((cck ^ ((r >> 1) & 3)) << 4);
            const __nv_bfloat16* src;
            bool ok = true;
            if (plane < 2) {
                int gm = m0 + r;
                src = (plane == 0 ? Ahi : Alo) + (long long)gm * lda + kb + cck * 8;
                ok = gm < M;
            } else {
                int gn = n0 + r;
                src = (plane == 2 ? Bhi : Blo) + (long long)gn * K + kb + cck * 8;
            }
            cpa16(dst, src, ok);
        }
    };

    const int kt_count = K >> 5;
    issue_load(0, 0); cp_commit();
    issue_load(1, 1); cp_commit();

    for (int kt = 0; kt < kt_count; kt++) {
        cp_wait1();
        __syncthreads();
        if (kt + 2 < kt_count) { issue_load((kt + 2) % 3, kt + 2); cp_commit(); }

        uint32_t sb = su + (kt % 3) * GSTAGE;
#pragma unroll
        for (int ks = 0; ks < 2; ks++) {
            uint32_t ah[4][4], al[4][4], bh[2][4], bl[2][4];
#pragma unroll
            for (int mi = 0; mi < 4; mi++) {
                int row = wm * 64 + mi * 16 + (lane & 15);
                int ch = 2 * ks + (lane >> 4);
                uint32_t a = sb + row * 64 + ((ch ^ ((row >> 1) & 3)) << 4);
                LDSM4(ah[mi], a);
                LDSM4(al[mi], a + 8192);
            }
#pragma unroll
            for (int np = 0; np < 2; np++) {
                int row = wn * 32 + np * 16 + ((lane >> 4) << 3) + (lane & 7);
                int ch = 2 * ks + ((lane >> 3) & 1);
                uint32_t a = sb + 16384 + row * 64 + ((ch ^ ((row >> 1) & 3)) << 4);
                LDSM4(bh[np], a);
                LDSM4(bl[np], a + 8192);
            }
#pragma unroll
            for (int mi = 0; mi < 4; mi++)
#pragma unroll
                for (int ni = 0; ni < 4; ni++) {
                    const uint32_t* bhp = &bh[ni >> 1][(ni & 1) * 2];
                    const uint32_t* blp = &bl[ni >> 1][(ni & 1) * 2];
                    mma16(c[mi][ni], ah[mi], bhp);
                    mma16(c[mi][ni], ah[mi], blp);
                    mma16(c[mi][ni], al[mi], bhp);
                }
        }
        __syncthreads();
    }

    // epilogue
#pragma unroll
    for (int mi = 0; mi < 4; mi++) {
#pragma unroll
        for (int ni = 0; ni < 4; ni++) {
            int row = m0 + wm * 64 + mi * 16 + lr;
            int col = n0 + wn * 32 + ni * 8 + lc * 2;
            float b0 = bias ? bias[col] : 0.f;
            float b1 = bias ? bias[col + 1] : 0.f;
            float v0 = c[mi][ni][0] + b0, v1 = c[mi][ni][1] + b1;
            float v2 = c[mi][ni][2] + b0, v3 = c[mi][ni][3] + b1;
            if (RELU) {
                v0 = fmaxf(v0, 0.f); v1 = fmaxf(v1, 0.f);
                v2 = fmaxf(v2, 0.f); v3 = fmaxf(v3, 0.f);
            }
            if (PLANES) {
                if (row < M) {
                    __nv_bfloat162 h = __floats2bfloat162_rn(v0, v1);
                    __nv_bfloat162 l = __floats2bfloat162_rn(
                        v0 - __bfloat162float(__low2bfloat16(h)),
                        v1 - __bfloat162float(__high2bfloat16(h)));
                    *(__nv_bfloat162*)(Chi + (long long)row * ldc + col) = h;
                    *(__nv_bfloat162*)(Clo + (long long)row * ldc + col) = l;
                }
                if (row + 8 < M) {
                    __nv_bfloat162 h = __floats2bfloat162_rn(v2, v3);
                    __nv_bfloat162 l = __floats2bfloat162_rn(
                        v2 - __bfloat162float(__low2bfloat16(h)),
                        v3 - __bfloat162float(__high2bfloat16(h)));
                    *(__nv_bfloat162*)(Chi + (long long)(row + 8) * ldc + col) = h;
                    *(__nv_bfloat162*)(Clo + (long long)(row + 8) * ldc + col) = l;
                }
            } else {
                if (row < M)
                    *(float2*)(C + (long long)row * ldc + col) = make_float2(v0, v1);
                if (row + 8 < M)
                    *(float2*)(C + (long long)(row + 8) * ldc + col) = make_float2(v2, v3);
            }
        }
    }
}

// ---------------- host launch ----------------
extern "C" void kernel_launch(void* const* d_in, const int* in_sizes, int n_in,
                              void* d_out, int out_size) {
    (void)in_sizes; (void)n_in; (void)out_size;
    const float* enc    = (const float*)d_in[0];
    const float* ehid   = (const float*)d_in[1];
    const int*   words  = (const int*)d_in[2];
    const float* embed  = (const float*)d_in[3];
    const float* Wih0   = (const float*)d_in[4];
    const float* Whh0   = (const float*)d_in[5];
    const float* bih0   = (const float*)d_in[6];
    const float* bhh0   = (const float*)d_in[7];
    const float* Wih1   = (const float*)d_in[8];
    const float* Whh1   = (const float*)d_in[9];
    const float* bih1   = (const float*)d_in[10];
    const float* bhh1   = (const float*)d_in[11];
    const float* attn_W = (const float*)d_in[12];
    const float* attn_b = (const float*)d_in[13];
    const float* aw_W   = (const float*)d_in[14];
    const float* aw_b   = (const float*)d_in[15];
    const float* out_W  = (const float*)d_in[16];
    const float* out_b  = (const float*)d_in[17];
    float* out = (float*)d_out;

    float *p_x, *p_gi, *p_h0, *p_sc;
    cudaGetSymbolAddress((void**)&p_x,  g_x);
    cudaGetSymbolAddress((void**)&p_gi, g_gi);
    cudaGetSymbolAddress((void**)&p_h0, g_hseq0);
    cudaGetSymbolAddress((void**)&p_sc, g_scores);

#define GETP(sym) \
    __nv_bfloat16 *sym##_h, *sym##_l; \
    cudaGetSymbolAddress((void**)&sym##_h, sym##_hi); \
    cudaGetSymbolAddress((void**)&sym##_l, sym##_lo);
    GETP(g_enc) GETP(g_attnW) GETP(g_proj) GETP(g_encT) GETP(g_attn)
    GETP(g_cat) GETP(g_awW) GETP(g_o) GETP(g_outW)
#undef GETP

    cudaFuncSetAttribute(bfx3_gemm<false, false>,
                         cudaFuncAttributeMaxDynamicSharedMemorySize, GSMEM);
    cudaFuncSetAttribute(bfx3_gemm<false, true>,
                         cudaFuncAttributeMaxDynamicSharedMemorySize, GSMEM);
    cudaFuncSetAttribute(bfx3_gemm<true, true>,
                         cudaFuncAttributeMaxDynamicSharedMemorySize, GSMEM);

    // ---- one-time splits of constant operands ----
    auto split = [&](const float* s, __nv_bfloat16* h, __nv_bfloat16* l, int n) {
        int n4 = n / 4;
        split_kernel<<<(n4 + 255) / 256, 256>>>(s, h, l, n4);
    };
    split(enc,    g_enc_h,   g_enc_l,   Bc * Sc * 2 * Hc);
    split(attn_W, g_attnW_h, g_attnW_l, Hc * 2 * Hc);
    split(aw_W,   g_awW_h,   g_awW_l,   H3c * H3c);
    split(out_W,  g_outW_h,  g_outW_l,  Vc * H3c);
    transpose_enc<<<dim3(32, 8, 32), dim3(32, 8)>>>(enc);
    embed_relu_kernel<<<ROWS, 128>>>(words, embed);

    // ---- layer 0 ----
    h0t_kernel<<<64, 256>>>(ehid, 0);
    simt_gemm<<<dim3(H3c / 64, ROWS / 64), 256>>>(p_x, Wih0, bih0, p_gi,
                                                  ROWS, H3c, Ec);
    for (int t = 0; t < Tc; t++)
        gru_step_kernel<<<128, 256>>>(Whh0, bhh0, t, 0);

    // ---- layer 1 ----
    h0t_kernel<<<64, 256>>>(ehid, 1);
    simt_gemm<<<dim3(H3c / 64, ROWS / 64), 256>>>(p_h0, Wih1, bih1, p_gi,
                                                  ROWS, H3c, Hc);
    for (int t = 0; t < Tc; t++)
        gru_step_kernel<<<128, 256>>>(Whh1, bhh1, t, 1);

    // ---- attention ----
    // proj = enc @ attn_W^T + attn_b  (M=8192 N=512 K=1024) -> planes
    bfx3_gemm<false, true><<<dim3(64, 4, 1), 256, GSMEM>>>(
        g_enc_h, g_enc_l, g_attnW_h, g_attnW_l, attn_b,
        nullptr, g_proj_h, g_proj_l,
        Bc * Sc, Hc, 2 * Hc, 2 * Hc, Hc, 0, 0, 0);
    // scores[b] = h[b] @ proj[b]^T  (M=64 N=256 K=512, batch 32) -> fp32
    bfx3_gemm<false, false><<<dim3(1, 2, 32), 256, GSMEM>>>(
        g_cat_h, g_cat_l, g_proj_h, g_proj_l, nullptr,
        p_sc, nullptr, nullptr,
        Tc, Sc, Hc, H3c, Sc,
        (long long)Tc * H3c, (long long)Sc * Hc, (long long)Tc * Sc);
    softmax_kernel<<<ROWS, 256>>>();
    // ctx[b] = attn[b] @ encT[b]^T  (M=64 N=1024 K=256) -> cat planes cols 512+
    bfx3_gemm<false, true><<<dim3(1, 8, 32), 256, GSMEM>>>(
        g_attn_h, g_attn_l, g_encT_h, g_encT_l, nullptr,
        nullptr, g_cat_h + Hc, g_cat_l + Hc,
        Tc, 2 * Hc, Sc, Sc, H3c,
        (long long)Tc * Sc, (long long)2 * Hc * Sc, (long long)Tc * H3c);

    // ---- output head ----
    bfx3_gemm<true, true><<<dim3(16, 12, 1), 256, GSMEM>>>(
        g_cat_h, g_cat_l, g_awW_h, g_awW_l, aw_b,
        nullptr, g_o_h, g_o_l,
        ROWS, H3c, H3c, H3c, H3c, 0, 0, 0);
    bfx3_gemm<false, false><<<dim3(16, 250, 1), 256, GSMEM>>>(
        g_o_h, g_o_l, g_outW_h, g_outW_l, out_b,
        out, nullptr, nullptr,
        ROWS, Vc, H3c, H3c, Vc, 0, 0, 0);
}

// round 6
// speedup vs baseline: 1.1155x; 1.1118x over previous
#include <cuda_runtime.h>
#include <cuda_bf16.h>
#include <cuda_fp16.h>
#include <cstdint>

#define DI __device__ __forceinline__

// ---------------- problem sizes ----------------
constexpr int Bc = 32, Sc = 256, Tc = 64, T1c = 65;
constexpr int Hc = 512, Ec = 300, Vc = 32000, H3c = 1536;
constexpr int ROWS = Bc * Tc;            // 2048

// ---------------- fp32 scratch ----------------
__device__ __align__(16) float g_x    [ROWS * Ec];
__device__ __align__(16) float g_gi   [ROWS * H3c];
__device__ __align__(16) float g_hta  [Hc * Bc];
__device__ __align__(16) float g_htb  [Hc * Bc];
__device__ __align__(16) float g_hseq0[ROWS * Hc];
__device__ __align__(16) float g_scores[ROWS * Sc];

// ---------------- bf16 hi/lo planes ----------------
#define PLANES_DECL(name, n) \
    __device__ __align__(16) __nv_bfloat16 name##_hi[n]; \
    __device__ __align__(16) __nv_bfloat16 name##_lo[n];

PLANES_DECL(g_enc,   Bc * Sc * 2 * Hc)
PLANES_DECL(g_attnW, Hc * 2 * Hc)
PLANES_DECL(g_proj,  Bc * Sc * Hc)
PLANES_DECL(g_encT,  Bc * 2 * Hc * Sc)
PLANES_DECL(g_attn,  ROWS * Sc)
PLANES_DECL(g_cat,   ROWS * H3c)
PLANES_DECL(g_awW,   H3c * H3c)

// ---------------- fp16 planes for logits path ----------------
__device__ __align__(16) __half g_o_fh [ROWS * H3c];
__device__ __align__(16) __half g_o_fl [ROWS * H3c];
__device__ __align__(16) __half g_outW_f[(long long)Vc * H3c];

// ---------------- helpers ----------------
DI void mma16(float c[4], const uint32_t a[4], const uint32_t b[2]) {
    asm volatile(
        "mma.sync.aligned.m16n8k16.row.col.f32.bf16.bf16.f32 "
        "{%0,%1,%2,%3}, {%4,%5,%6,%7}, {%8,%9}, {%0,%1,%2,%3};"
        : "+f"(c[0]), "+f"(c[1]), "+f"(c[2]), "+f"(c[3])
        : "r"(a[0]), "r"(a[1]), "r"(a[2]), "r"(a[3]), "r"(b[0]), "r"(b[1]));
}
DI void mma16h(float c[4], const uint32_t a[4], const uint32_t b[2]) {
    asm volatile(
        "mma.sync.aligned.m16n8k16.row.col.f32.f16.f16.f32 "
        "{%0,%1,%2,%3}, {%4,%5,%6,%7}, {%8,%9}, {%0,%1,%2,%3};"
        : "+f"(c[0]), "+f"(c[1]), "+f"(c[2]), "+f"(c[3])
        : "r"(a[0]), "r"(a[1]), "r"(a[2]), "r"(a[3]), "r"(b[0]), "r"(b[1]));
}
#define LDSM4(R, addr) \
    asm volatile("ldmatrix.sync.aligned.m8n8.x4.shared.b16 {%0,%1,%2,%3}, [%4];" \
                 : "=r"((R)[0]), "=r"((R)[1]), "=r"((R)[2]), "=r"((R)[3]) : "r"(addr))

DI void cpa16(uint32_t dst, const void* src, bool ok) {
    int sz = ok ? 16 : 0;
    asm volatile("cp.async.cg.shared.global [%0], [%1], 16, %2;\n"
                 :: "r"(dst), "l"(src), "r"(sz));
}
DI void cpa16u(uint32_t dst, const void* src) {
    asm volatile("cp.async.cg.shared.global [%0], [%1], 16;\n"
                 :: "r"(dst), "l"(src));
}
DI void cp_commit() { asm volatile("cp.async.commit_group;\n"); }
DI void cp_wait1()  { asm volatile("cp.async.wait_group 1;\n"); }
DI void cp_wait0()  { asm volatile("cp.async.wait_group 0;\n"); }

DI void splits(float v, __nv_bfloat16& h, __nv_bfloat16& l) {
    h = __float2bfloat16(v);
    l = __float2bfloat16(v - __bfloat162float(h));
}

// ---------------- fp32 -> bf16 hi/lo plane split ----------------
__global__ void split_kernel(const float* __restrict__ s,
                             __nv_bfloat16* __restrict__ hi,
                             __nv_bfloat16* __restrict__ lo, int n4) {
    int i = blockIdx.x * blockDim.x + threadIdx.x;
    if (i >= n4) return;
    float4 v = ((const float4*)s)[i];
    __nv_bfloat162 h0 = __floats2bfloat162_rn(v.x, v.y);
    __nv_bfloat162 h1 = __floats2bfloat162_rn(v.z, v.w);
    __nv_bfloat162 l0 = __floats2bfloat162_rn(v.x - __bfloat162float(__low2bfloat16(h0)),
                                              v.y - __bfloat162float(__high2bfloat16(h0)));
    __nv_bfloat162 l1 = __floats2bfloat162_rn(v.z - __bfloat162float(__low2bfloat16(h1)),
                                              v.w - __bfloat162float(__high2bfloat16(h1)));
    ((__nv_bfloat162*)hi)[2 * i] = h0;
    ((__nv_bfloat162*)hi)[2 * i + 1] = h1;
    ((__nv_bfloat162*)lo)[2 * i] = l0;
    ((__nv_bfloat162*)lo)[2 * i + 1] = l1;
}

// ---------------- fp32 -> single fp16 plane ----------------
__global__ void split_half_kernel(const float* __restrict__ s,
                                  __half* __restrict__ h, int n4) {
    int i = blockIdx.x * blockDim.x + threadIdx.x;
    if (i >= n4) return;
    float4 v = ((const float4*)s)[i];
    ((__half2*)h)[2 * i]     = __floats2half2_rn(v.x, v.y);
    ((__half2*)h)[2 * i + 1] = __floats2half2_rn(v.z, v.w);
}

// ---------------- embed gather + relu ----------------
__global__ void embed_relu_kernel(const int* __restrict__ words,
                                  const float* __restrict__ embed) {
    int row = blockIdx.x;
    int b = row >> 6, t = row & 63;
    int w = words[b * T1c + t];
    const float* e = embed + (long long)w * Ec;
    float* x = g_x + (long long)row * Ec;
    for (int i = threadIdx.x; i < Ec; i += blockDim.x)
        x[i] = fmaxf(e[i], 0.f);
}

// ---------------- h0 (transposed) ----------------
__global__ void h0t_kernel(const float* __restrict__ ehid, int layer) {
    int i = blockIdx.x * blockDim.x + threadIdx.x;
    if (i < Bc * Hc) {
        int b = i >> 9, j = i & 511;
        g_hta[j * Bc + b] = ehid[layer * Bc * Hc + i] + ehid[(layer + 2) * Bc * Hc + i];
    }
}

// ------------- encoder transpose [b][s][d] -> [b][d][s] planes -------------
__global__ void transpose_enc(const float* __restrict__ enc) {
    __shared__ float t[32][33];
    int b = blockIdx.z;
    int d0 = blockIdx.x * 32, s0 = blockIdx.y * 32;
    int tx = threadIdx.x, ty = threadIdx.y;
#pragma unroll
    for (int i = 0; i < 4; i++)
        t[ty + 8 * i][tx] =
            enc[((long long)b * Sc + s0 + ty + 8 * i) * (2 * Hc) + d0 + tx];
    __syncthreads();
#pragma unroll
    for (int i = 0; i < 4; i++) {
        float v = t[tx][ty + 8 * i];
        long long idx = ((long long)b * (2 * Hc) + d0 + ty + 8 * i) * Sc + s0 + tx;
        __nv_bfloat16 h, l; splits(v, h, l);
        g_encT_hi[idx] = h; g_encT_lo[idx] = l;
    }
}

// ---------------- fp32 SIMT GEMM (gi): C = A @ W^T + bias ----------------
__global__ void __launch_bounds__(256)
simt_gemm(const float* __restrict__ A, const float* __restrict__ W,
          const float* __restrict__ bias, float* __restrict__ C,
          int M, int N, int K) {
    __shared__ float As[16 * 68];
    __shared__ float Bs[16 * 68];
    int tid = threadIdx.x;
    int tx = tid & 15, ty = tid >> 4;
    int m0 = blockIdx.y * 64, n0 = blockIdx.x * 64;
    float c[4][4] = {};
    int kt_count = (K + 15) / 16;
    for (int kt = 0; kt < kt_count; kt++) {
        int k0 = kt * 16;
        __syncthreads();
#pragma unroll
        for (int e = tid; e < 1024; e += 256) {
            int r = e >> 4, k = e & 15;
            As[k * 68 + r] = (k0 + k < K) ? A[(long long)(m0 + r) * K + k0 + k] : 0.f;
            Bs[k * 68 + r] = (k0 + k < K) ? W[(long long)(n0 + r) * K + k0 + k] : 0.f;
        }
        __syncthreads();
#pragma unroll
        for (int k = 0; k < 16; k++) {
            float4 a = *(const float4*)&As[k * 68 + ty * 4];
            float4 b = *(const float4*)&Bs[k * 68 + tx * 4];
            float av[4] = {a.x, a.y, a.z, a.w};
            float bv[4] = {b.x, b.y, b.z, b.w};
#pragma unroll
            for (int i = 0; i < 4; i++)
#pragma unroll
                for (int j = 0; j < 4; j++)
                    c[i][j] += av[i] * bv[j];
        }
    }
#pragma unroll
    for (int i = 0; i < 4; i++)
#pragma unroll
        for (int j = 0; j < 4; j++) {
            int row = m0 + ty * 4 + i, col = n0 + tx * 4 + j;
            C[(long long)row * N + col] = c[i][j] + bias[col];
        }
}

// ---------------- fused GRU step ----------------
__global__ void __launch_bounds__(256)
gru_step_kernel(const float* __restrict__ Whh, const float* __restrict__ bhh,
                int t, int layer) {
    __shared__ float sp[3][4][32];
    const float* hin = (t & 1) ? g_htb : g_hta;
    float* hout      = (t & 1) ? g_hta : g_htb;

    int tid = threadIdx.x;
    int b  = tid & 31;
    int jl = (tid >> 5) & 3;
    int kh = tid >> 7;
    int j  = blockIdx.x * 4 + jl;

    const float* wr = Whh + (long long)j * Hc;
    const float* wz = wr + (long long)Hc * Hc;
    const float* wn = wr + (long long)2 * Hc * Hc;

    float ar = 0.f, az = 0.f, an = 0.f;
    int k0 = kh * 256;
#pragma unroll 4
    for (int k = k0; k < k0 + 256; k += 4) {
        float4 r4 = *(const float4*)(wr + k);
        float4 z4 = *(const float4*)(wz + k);
        float4 n4 = *(const float4*)(wn + k);
        float h0v = hin[(k + 0) * Bc + b];
        float h1v = hin[(k + 1) * Bc + b];
        float h2v = hin[(k + 2) * Bc + b];
        float h3v = hin[(k + 3) * Bc + b];
        ar += r4.x * h0v + r4.y * h1v + r4.z * h2v + r4.w * h3v;
        az += z4.x * h0v + z4.y * h1v + z4.z * h2v + z4.w * h3v;
        an += n4.x * h0v + n4.y * h1v + n4.z * h2v + n4.w * h3v;
    }
    if (kh) {
        sp[0][jl][b] = ar; sp[1][jl][b] = az; sp[2][jl][b] = an;
    }
    __syncthreads();
    if (!kh) {
        ar += sp[0][jl][b]; az += sp[1][jl][b]; an += sp[2][jl][b];
        int row = b * Tc + t;
        const float* g = g_gi + (long long)row * H3c;
        float grv = g[j] + ar + bhh[j];
        float gzv = g[j + Hc] + az + bhh[j + Hc];
        float ghn = an + bhh[j + 2 * Hc];
        float r = 1.f / (1.f + expf(-grv));
        float z = 1.f / (1.f + expf(-gzv));
        float n = tanhf(g[j + 2 * Hc] + r * ghn);
        float hold = hin[j * Bc + b];
        float hnew = (1.f - z) * n + z * hold;
        hout[j * Bc + b] = hnew;
        if (layer == 0) {
            g_hseq0[(long long)row * Hc + j] = hnew;
        } else {
            __nv_bfloat16 h, l; splits(hnew, h, l);
            g_cat_hi[(long long)row * H3c + j] = h;
            g_cat_lo[(long long)row * H3c + j] = l;
        }
    }
}

// ---------------- softmax (256 wide) -> attn planes ----------------
__global__ void softmax_kernel() {
    int row = blockIdx.x, tid = threadIdx.x;
    __shared__ float sm_[8], ss_[8];
    float v = g_scores[(long long)row * Sc + tid];
    float m = v;
#pragma unroll
    for (int o = 16; o; o >>= 1) m = fmaxf(m, __shfl_xor_sync(~0u, m, o));
    if ((tid & 31) == 0) sm_[tid >> 5] = m;
    __syncthreads();
    float mm = sm_[0];
#pragma unroll
    for (int i = 1; i < 8; i++) mm = fmaxf(mm, sm_[i]);
    float e = expf(v - mm);
    float s = e;
#pragma unroll
    for (int o = 16; o; o >>= 1) s += __shfl_xor_sync(~0u, s, o);
    if ((tid & 31) == 0) ss_[tid >> 5] = s;
    __syncthreads();
    float tot = 0.f;
#pragma unroll
    for (int i = 0; i < 8; i++) tot += ss_[i];
    float p = e / tot;
    __nv_bfloat16 h, l; splits(p, h, l);
    g_attn_hi[(long long)row * Sc + tid] = h;
    g_attn_lo[(long long)row * Sc + tid] = l;
}

// ======================= bf16x3 pipelined tensor GEMM =======================
// OUT: 0 = fp32 C (+bias), 1 = bf16 hi/lo planes, 2 = fp16 hi/lo planes.
constexpr int GSTAGE = 32768;
constexpr int GSMEM  = 3 * GSTAGE;

template <bool RELU, int OUT>
__global__ void __launch_bounds__(256, 1)
bfx3_gemm(const __nv_bfloat16* __restrict__ Ahi, const __nv_bfloat16* __restrict__ Alo,
          const __nv_bfloat16* __restrict__ Bhi, const __nv_bfloat16* __restrict__ Blo,
          const float* __restrict__ bias, float* __restrict__ C,
          void* __restrict__ Chi_, void* __restrict__ Clo_,
          int M, int N, int K, int lda, int ldc,
          long long sA, long long sB, long long sC) {
    extern __shared__ char smem[];
    uint32_t su = (uint32_t)__cvta_generic_to_shared(smem);

    Ahi += (long long)blockIdx.z * sA;  Alo += (long long)blockIdx.z * sA;
    Bhi += (long long)blockIdx.z * sB;  Blo += (long long)blockIdx.z * sB;

    const int m0 = blockIdx.x * 128, n0 = blockIdx.y * 128;
    const int tid = threadIdx.x;
    const int lane = tid & 31, wid = tid >> 5;
    const int wm = wid & 1, wn = wid >> 1;
    const int lr = lane >> 2, lc = lane & 3;

    float c[4][4][4] = {};

    auto issue_load = [&](int stage, int kt) {
        int kb = kt * 32;
        uint32_t sb = su + stage * GSTAGE;
#pragma unroll
        for (int i = 0; i < 8; i++) {
            int chunkid = tid + 256 * i;
            int plane = chunkid >> 9;
            int w = chunkid & 511;
            int r = w >> 2, cck = w & 3;
            uint32_t dst = sb + plane * 8192 + r * 64 + ((cck ^ ((r >> 1) & 3)) << 4);
            const __nv_bfloat16* src;
            bool ok = true;
            if (plane < 2) {
                int gm = m0 + r;
                src = (plane == 0 ? Ahi : Alo) + (long long)gm * lda + kb + cck * 8;
                ok = gm < M;
            } else {
                int gn = n0 + r;
                src = (plane == 2 ? Bhi : Blo) + (long long)gn * K + kb + cck * 8;
            }
            cpa16(dst, src, ok);
        }
    };

    const int kt_count = K >> 5;
    issue_load(0, 0); cp_commit();
    issue_load(1, 1); cp_commit();

    for (int kt = 0; kt < kt_count; kt++) {
        if (kt + 2 < kt_count) cp_wait1(); else cp_wait0();
        __syncthreads();
        if (kt + 2 < kt_count) { issue_load((kt + 2) % 3, kt + 2); cp_commit(); }

        uint32_t sb = su + (kt % 3) * GSTAGE;
#pragma unroll
        for (int ks = 0; ks < 2; ks++) {
            uint32_t ah[4][4], al[4][4], bh[2][4], bl[2][4];
#pragma unroll
            for (int mi = 0; mi < 4; mi++) {
                int row = wm * 64 + mi * 16 + (lane & 15);
                int ch = 2 * ks + (lane >> 4);
                uint32_t a = sb + row * 64 + ((ch ^ ((row >> 1) & 3)) << 4);
                LDSM4(ah[mi], a);
                LDSM4(al[mi], a + 8192);
            }
#pragma unroll
            for (int np = 0; np < 2; np++) {
                int row = wn * 32 + np * 16 + ((lane >> 4) << 3) + (lane & 7);
                int ch = 2 * ks + ((lane >> 3) & 1);
                uint32_t a = sb + 16384 + row * 64 + ((ch ^ ((row >> 1) & 3)) << 4);
                LDSM4(bh[np], a);
                LDSM4(bl[np], a + 8192);
            }
            // term-outermost ordering: consecutive MMAs hit different accumulators
#pragma unroll
            for (int mi = 0; mi < 4; mi++)
#pragma unroll
                for (int ni = 0; ni < 4; ni++)
                    mma16(c[mi][ni], ah[mi], &bh[ni >> 1][(ni & 1) * 2]);
#pragma unroll
            for (int mi = 0; mi < 4; mi++)
#pragma unroll
                for (int ni = 0; ni < 4; ni++)
                    mma16(c[mi][ni], ah[mi], &bl[ni >> 1][(ni & 1) * 2]);
#pragma unroll
            for (int mi = 0; mi < 4; mi++)
#pragma unroll
                for (int ni = 0; ni < 4; ni++)
                    mma16(c[mi][ni], al[mi], &bh[ni >> 1][(ni & 1) * 2]);
        }
        __syncthreads();
    }

#pragma unroll
    for (int mi = 0; mi < 4; mi++) {
#pragma unroll
        for (int ni = 0; ni < 4; ni++) {
            int row = m0 + wm * 64 + mi * 16 + lr;
            int col = n0 + wn * 32 + ni * 8 + lc * 2;
            float b0 = bias ? bias[col] : 0.f;
            float b1 = bias ? bias[col + 1] : 0.f;
            float v0 = c[mi][ni][0] + b0, v1 = c[mi][ni][1] + b1;
            float v2 = c[mi][ni][2] + b0, v3 = c[mi][ni][3] + b1;
            if (RELU) {
                v0 = fmaxf(v0, 0.f); v1 = fmaxf(v1, 0.f);
                v2 = fmaxf(v2, 0.f); v3 = fmaxf(v3, 0.f);
            }
            if (OUT == 0) {
                float* Cz = C + (long long)blockIdx.z * sC;
                if (row < M)
                    *(float2*)(Cz + (long long)row * ldc + col) = make_float2(v0, v1);
                if (row + 8 < M)
                    *(float2*)(Cz + (long long)(row + 8) * ldc + col) = make_float2(v2, v3);
            } else if (OUT == 1) {
                __nv_bfloat16* Chi = (__nv_bfloat16*)Chi_ + (long long)blockIdx.z * sC;
                __nv_bfloat16* Clo = (__nv_bfloat16*)Clo_ + (long long)blockIdx.z * sC;
                if (row < M) {
                    __nv_bfloat162 h = __floats2bfloat162_rn(v0, v1);
                    __nv_bfloat162 l = __floats2bfloat162_rn(
                        v0 - __bfloat162float(__low2bfloat16(h)),
                        v1 - __bfloat162float(__high2bfloat16(h)));
                    *(__nv_bfloat162*)(Chi + (long long)row * ldc + col) = h;
                    *(__nv_bfloat162*)(Clo + (long long)row * ldc + col) = l;
                }
                if (row + 8 < M) {
                    __nv_bfloat162 h = __floats2bfloat162_rn(v2, v3);
                    __nv_bfloat162 l = __floats2bfloat162_rn(
                        v2 - __bfloat162float(__low2bfloat16(h)),
                        v3 - __bfloat162float(__high2bfloat16(h)));
                    *(__nv_bfloat162*)(Chi + (long long)(row + 8) * ldc + col) = h;
                    *(__nv_bfloat162*)(Clo + (long long)(row + 8) * ldc + col) = l;
                }
            } else {
                __half* Chi = (__half*)Chi_ + (long long)blockIdx.z * sC;
                __half* Clo = (__half*)Clo_ + (long long)blockIdx.z * sC;
                if (row < M) {
                    __half2 h = __floats2half2_rn(v0, v1);
                    __half2 l = __floats2half2_rn(
                        v0 - __half2float(__low2half(h)),
                        v1 - __half2float(__high2half(h)));
                    *(__half2*)(Chi + (long long)row * ldc + col) = h;
                    *(__half2*)(Clo + (long long)row * ldc + col) = l;
                }
                if (row + 8 < M) {
                    __half2 h = __floats2half2_rn(v2, v3);
                    __half2 l = __floats2half2_rn(
                        v2 - __half2float(__low2half(h)),
                        v3 - __half2float(__high2half(h)));
                    *(__half2*)(Chi + (long long)(row + 8) * ldc + col) = h;
                    *(__half2*)(Clo + (long long)(row + 8) * ldc + col) = l;
                }
            }
        }
    }
}

// ============ fp16 2-term GEMM for logits: C = (Ahi+Alo) @ Bf^T + bias ============
// A fp16 hi/lo planes [M][lda], B single fp16 [N][K]. M%128==0, N%128==0, K%32==0.
constexpr int HSTAGE = 24576;
constexpr int HSMEM  = 3 * HSTAGE;

__global__ void __launch_bounds__(256, 1)
fp16_gemm(const __half* __restrict__ Ahi, const __half* __restrict__ Alo,
          const __half* __restrict__ Bf,
          const float* __restrict__ bias, float* __restrict__ C,
          int M, int N, int K, int lda, int ldc) {
    extern __shared__ char smem[];
    uint32_t su = (uint32_t)__cvta_generic_to_shared(smem);

    const int m0 = blockIdx.x * 128, n0 = blockIdx.y * 128;
    const int tid = threadIdx.x;
    const int lane = tid & 31, wid = tid >> 5;
    const int wm = wid & 1, wn = wid >> 1;
    const int lr = lane >> 2, lc = lane & 3;

    float c[4][4][4] = {};

    auto issue_load = [&](int stage, int kt) {
        int kb = kt * 32;
        uint32_t sb = su + stage * HSTAGE;
#pragma unroll
        for (int i = 0; i < 6; i++) {
            int chunkid = tid + 256 * i;
            int plane = chunkid >> 9;
            int w = chunkid & 511;
            int r = w >> 2, cck = w & 3;
            uint32_t dst = sb + plane * 8192 + r * 64 + ((cck ^ ((r >> 1) & 3)) << 4);
            const __half* src;
            if (plane == 0)      src = Ahi + (long long)(m0 + r) * lda + kb + cck * 8;
            else if (plane == 1) src = Alo + (long long)(m0 + r) * lda + kb + cck * 8;
            else                 src = Bf  + (long long)(n0 + r) * K   + kb + cck * 8;
            cpa16u(dst, src);
        }
    };

    const int kt_count = K >> 5;
    issue_load(0, 0); cp_commit();
    issue_load(1, 1); cp_commit();

    for (int kt = 0; kt < kt_count; kt++) {
        if (kt + 2 < kt_count) cp_wait1(); else cp_wait0();
        __syncthreads();
        if (kt + 2 < kt_count) { issue_load((kt + 2) % 3, kt + 2); cp_commit(); }

        uint32_t sb = su + (kt % 3) * HSTAGE;
#pragma unroll
        for (int ks = 0; ks < 2; ks++) {
            uint32_t ah[4][4], al[4][4], bh[2][4];
#pragma unroll
            for (int mi = 0; mi < 4; mi++) {
                int row = wm * 64 + mi * 16 + (lane & 15);
                int ch = 2 * ks + (lane >> 4);
                uint32_t a = sb + row * 64 + ((ch ^ ((row >> 1) & 3)) << 4);
                LDSM4(ah[mi], a);
                LDSM4(al[mi], a + 8192);
            }
#pragma unroll
            for (int np = 0; np < 2; np++) {
                int row = wn * 32 + np * 16 + ((lane >> 4) << 3) + (lane & 7);
                int ch = 2 * ks + ((lane >> 3) & 1);
                uint32_t a = sb + 16384 + row * 64 + ((ch ^ ((row >> 1) & 3)) << 4);
                LDSM4(bh[np], a);
            }
#pragma unroll
            for (int mi = 0; mi < 4; mi++)
#pragma unroll
                for (int ni = 0; ni < 4; ni++)
                    mma16h(c[mi][ni], ah[mi], &bh[ni >> 1][(ni & 1) * 2]);
#pragma unroll
            for (int mi = 0; mi < 4; mi++)
#pragma unroll
                for (int ni = 0; ni < 4; ni++)
                    mma16h(c[mi][ni], al[mi], &bh[ni >> 1][(ni & 1) * 2]);
        }
        __syncthreads();
    }

#pragma unroll
    for (int mi = 0; mi < 4; mi++) {
#pragma unroll
        for (int ni = 0; ni < 4; ni++) {
            int row = m0 + wm * 64 + mi * 16 + lr;
            int col = n0 + wn * 32 + ni * 8 + lc * 2;
            float b0 = bias[col], b1 = bias[col + 1];
            *(float2*)(C + (long long)row * ldc + col) =
                make_float2(c[mi][ni][0] + b0, c[mi][ni][1] + b1);
            *(float2*)(C + (long long)(row + 8) * ldc + col) =
                make_float2(c[mi][ni][2] + b0, c[mi][ni][3] + b1);
        }
    }
}

// ---------------- host launch ----------------
extern "C" void kernel_launch(void* const* d_in, const int* in_sizes, int n_in,
                              void* d_out, int out_size) {
    (void)in_sizes; (void)n_in; (void)out_size;
    const float* enc    = (const float*)d_in[0];
    const float* ehid   = (const float*)d_in[1];
    const int*   words  = (const int*)d_in[2];
    const float* embed  = (const float*)d_in[3];
    const float* Wih0   = (const float*)d_in[4];
    const float* Whh0   = (const float*)d_in[5];
    const float* bih0   = (const float*)d_in[6];
    const float* bhh0   = (const float*)d_in[7];
    const float* Wih1   = (const float*)d_in[8];
    const float* Whh1   = (const float*)d_in[9];
    const float* bih1   = (const float*)d_in[10];
    const float* bhh1   = (const float*)d_in[11];
    const float* attn_W = (const float*)d_in[12];
    const float* attn_b = (const float*)d_in[13];
    const float* aw_W   = (const float*)d_in[14];
    const float* aw_b   = (const float*)d_in[15];
    const float* out_W  = (const float*)d_in[16];
    const float* out_b  = (const float*)d_in[17];
    float* out = (float*)d_out;

    float *p_x, *p_gi, *p_h0, *p_sc;
    cudaGetSymbolAddress((void**)&p_x,  g_x);
    cudaGetSymbolAddress((void**)&p_gi, g_gi);
    cudaGetSymbolAddress((void**)&p_h0, g_hseq0);
    cudaGetSymbolAddress((void**)&p_sc, g_scores);

#define GETP(sym) \
    __nv_bfloat16 *sym##_h, *sym##_l; \
    cudaGetSymbolAddress((void**)&sym##_h, sym##_hi); \
    cudaGetSymbolAddress((void**)&sym##_l, sym##_lo);
    GETP(g_enc) GETP(g_attnW) GETP(g_proj) GETP(g_encT) GETP(g_attn)
    GETP(g_cat) GETP(g_awW)
#undef GETP
    __half *p_ofh, *p_ofl, *p_wf;
    cudaGetSymbolAddress((void**)&p_ofh, g_o_fh);
    cudaGetSymbolAddress((void**)&p_ofl, g_o_fl);
    cudaGetSymbolAddress((void**)&p_wf,  g_outW_f);

    cudaFuncSetAttribute(bfx3_gemm<false, 0>,
                         cudaFuncAttributeMaxDynamicSharedMemorySize, GSMEM);
    cudaFuncSetAttribute(bfx3_gemm<false, 1>,
                         cudaFuncAttributeMaxDynamicSharedMemorySize, GSMEM);
    cudaFuncSetAttribute(bfx3_gemm<true, 2>,
                         cudaFuncAttributeMaxDynamicSharedMemorySize, GSMEM);
    cudaFuncSetAttribute(fp16_gemm,
                         cudaFuncAttributeMaxDynamicSharedMemorySize, HSMEM);

    auto split = [&](const float* s, __nv_bfloat16* h, __nv_bfloat16* l, int n) {
        int n4 = n / 4;
        split_kernel<<<(n4 + 255) / 256, 256>>>(s, h, l, n4);
    };
    split(enc,    g_enc_h,   g_enc_l,   Bc * Sc * 2 * Hc);
    split(attn_W, g_attnW_h, g_attnW_l, Hc * 2 * Hc);
    split(aw_W,   g_awW_h,   g_awW_l,   H3c * H3c);
    {
        int n4 = Vc * H3c / 4;
        split_half_kernel<<<(n4 + 255) / 256, 256>>>(out_W, p_wf, n4);
    }
    transpose_enc<<<dim3(32, 8, 32), dim3(32, 8)>>>(enc);
    embed_relu_kernel<<<ROWS, 128>>>(words, embed);

    // proj = enc @ attn_W^T + attn_b  (M=8192 N=512 K=1024) -> bf16 planes
    bfx3_gemm<false, 1><<<dim3(64, 4, 1), 256, GSMEM>>>(
        g_enc_h, g_enc_l, g_attnW_h, g_attnW_l, attn_b,
        nullptr, g_proj_h, g_proj_l,
        Bc * Sc, Hc, 2 * Hc, 2 * Hc, Hc, 0, 0, 0);

    // ---- layer 0 ----
    h0t_kernel<<<64, 256>>>(ehid, 0);
    simt_gemm<<<dim3(H3c / 64, ROWS / 64), 256>>>(p_x, Wih0, bih0, p_gi,
                                                  ROWS, H3c, Ec);
    for (int t = 0; t < Tc; t++)
        gru_step_kernel<<<128, 256>>>(Whh0, bhh0, t, 0);

    // ---- layer 1 ----
    h0t_kernel<<<64, 256>>>(ehid, 1);
    simt_gemm<<<dim3(H3c / 64, ROWS / 64), 256>>>(p_h0, Wih1, bih1, p_gi,
                                                  ROWS, H3c, Hc);
    for (int t = 0; t < Tc; t++)
        gru_step_kernel<<<128, 256>>>(Whh1, bhh1, t, 1);

    // scores[b] = h[b] @ proj[b]^T  (M=64 N=256 K=512, batch 32) -> fp32
    bfx3_gemm<false, 0><<<dim3(1, 2, 32), 256, GSMEM>>>(
        g_cat_h, g_cat_l, g_proj_h, g_proj_l, nullptr,
        p_sc, nullptr, nullptr,
        Tc, Sc, Hc, H3c, Sc,
        (long long)Tc * H3c, (long long)Sc * Hc, (long long)Tc * Sc);
    softmax_kernel<<<ROWS, 256>>>();
    // ctx[b] = attn[b] @ encT[b]^T  (M=64 N=1024 K=256) -> cat planes cols 512+
    bfx3_gemm<false, 1><<<dim3(1, 8, 32), 256, GSMEM>>>(
        g_attn_h, g_attn_l, g_encT_h, g_encT_l, nullptr,
        nullptr, g_cat_h + Hc, g_cat_l + Hc,
        Tc, 2 * Hc, Sc, Sc, H3c,
        (long long)Tc * Sc, (long long)2 * Hc * Sc, (long long)Tc * H3c);

    // o = relu(cat @ aw_W^T + aw_b)  (M=2048 N=1536 K=1536) -> fp16 planes
    bfx3_gemm<true, 2><<<dim3(16, 12, 1), 256, GSMEM>>>(
        g_cat_h, g_cat_l, g_awW_h, g_awW_l, aw_b,
        nullptr, p_ofh, p_ofl,
        ROWS, H3c, H3c, H3c, H3c, 0, 0, 0);

    // logits = o @ out_W^T + out_b  (M=2048 N=32000 K=1536) -> fp32 out
    fp16_gemm<<<dim3(16, 250), 256, HSMEM>>>(
        p_ofh, p_ofl, p_wf, out_b, out,
        ROWS, Vc, H3c, H3c, Vc);
}

// round 7
// speedup vs baseline: 2.5150x; 2.2545x over previous
#include <cuda_runtime.h>
#include <cuda_bf16.h>
#include <cuda_fp16.h>
#include <cstdint>

#define DI __device__ __forceinline__

// ---------------- problem sizes ----------------
constexpr int Bc = 32, Sc = 256, Tc = 64, T1c = 65;
constexpr int Hc = 512, Ec = 300, Vc = 32000, H3c = 1536;
constexpr int ROWS = Bc * Tc;            // 2048

// ---------------- fp32 scratch ----------------
__device__ __align__(16) float g_x    [ROWS * Ec];
__device__ __align__(16) float g_gi   [ROWS * H3c];
__device__ __align__(16) float g_hta  [Hc * Bc];
__device__ __align__(16) float g_htb  [Hc * Bc];
__device__ __align__(16) float g_hseq0[ROWS * Hc];
__device__ __align__(16) float g_scores[ROWS * Sc];
__device__ int g_bar_ctr;

// ---------------- bf16 hi/lo planes ----------------
#define PLANES_DECL(name, n) \
    __device__ __align__(16) __nv_bfloat16 name##_hi[n]; \
    __device__ __align__(16) __nv_bfloat16 name##_lo[n];

PLANES_DECL(g_proj,  Bc * Sc * Hc)
PLANES_DECL(g_encT,  Bc * 2 * Hc * Sc)
PLANES_DECL(g_attn,  ROWS * Sc)
PLANES_DECL(g_cat,   ROWS * H3c)
PLANES_DECL(g_awW,   H3c * H3c)

// ---------------- fp16 planes ----------------
__device__ __align__(16) __half g_enc_fh[Bc * Sc * 2 * Hc];
__device__ __align__(16) __half g_enc_fl[Bc * Sc * 2 * Hc];
__device__ __align__(16) __half g_attnW_f[Hc * 2 * Hc];
__device__ __align__(16) __half g_o_f  [ROWS * H3c];
__device__ __align__(16) __half g_outW_f[(long long)Vc * H3c];

// ---------------- helpers ----------------
DI void mma16(float c[4], const uint32_t a[4], const uint32_t b[2]) {
    asm volatile(
        "mma.sync.aligned.m16n8k16.row.col.f32.bf16.bf16.f32 "
        "{%0,%1,%2,%3}, {%4,%5,%6,%7}, {%8,%9}, {%0,%1,%2,%3};"
        : "+f"(c[0]), "+f"(c[1]), "+f"(c[2]), "+f"(c[3])
        : "r"(a[0]), "r"(a[1]), "r"(a[2]), "r"(a[3]), "r"(b[0]), "r"(b[1]));
}
DI void mma16h(float c[4], const uint32_t a[4], const uint32_t b[2]) {
    asm volatile(
        "mma.sync.aligned.m16n8k16.row.col.f32.f16.f16.f32 "
        "{%0,%1,%2,%3}, {%4,%5,%6,%7}, {%8,%9}, {%0,%1,%2,%3};"
        : "+f"(c[0]), "+f"(c[1]), "+f"(c[2]), "+f"(c[3])
        : "r"(a[0]), "r"(a[1]), "r"(a[2]), "r"(a[3]), "r"(b[0]), "r"(b[1]));
}
#define LDSM4(R, addr) \
    asm volatile("ldmatrix.sync.aligned.m8n8.x4.shared.b16 {%0,%1,%2,%3}, [%4];" \
                 : "=r"((R)[0]), "=r"((R)[1]), "=r"((R)[2]), "=r"((R)[3]) : "r"(addr))

DI void cpa16(uint32_t dst, const void* src, bool ok) {
    int sz = ok ? 16 : 0;
    asm volatile("cp.async.cg.shared.global [%0], [%1], 16, %2;\n"
                 :: "r"(dst), "l"(src), "r"(sz));
}
DI void cpa16u(uint32_t dst, const void* src) {
    asm volatile("cp.async.cg.shared.global [%0], [%1], 16;\n"
                 :: "r"(dst), "l"(src));
}
DI void cp_commit() { asm volatile("cp.async.commit_group;\n"); }
DI void cp_wait1()  { asm volatile("cp.async.wait_group 1;\n"); }
DI void cp_wait0()  { asm volatile("cp.async.wait_group 0;\n"); }

DI void splits(float v, __nv_bfloat16& h, __nv_bfloat16& l) {
    h = __float2bfloat16(v);
    l = __float2bfloat16(v - __bfloat162float(h));
}

// ---------------- split kernels ----------------
__global__ void split_kernel(const float* __restrict__ s,
                             __nv_bfloat16* __restrict__ hi,
                             __nv_bfloat16* __restrict__ lo, int n4) {
    int i = blockIdx.x * blockDim.x + threadIdx.x;
    if (i >= n4) return;
    float4 v = ((const float4*)s)[i];
    __nv_bfloat162 h0 = __floats2bfloat162_rn(v.x, v.y);
    __nv_bfloat162 h1 = __floats2bfloat162_rn(v.z, v.w);
    __nv_bfloat162 l0 = __floats2bfloat162_rn(v.x - __bfloat162float(__low2bfloat16(h0)),
                                              v.y - __bfloat162float(__high2bfloat16(h0)));
    __nv_bfloat162 l1 = __floats2bfloat162_rn(v.z - __bfloat162float(__low2bfloat16(h1)),
                                              v.w - __bfloat162float(__high2bfloat16(h1)));
    ((__nv_bfloat162*)hi)[2 * i] = h0;
    ((__nv_bfloat162*)hi)[2 * i + 1] = h1;
    ((__nv_bfloat162*)lo)[2 * i] = l0;
    ((__nv_bfloat162*)lo)[2 * i + 1] = l1;
}

__global__ void split_half_kernel(const float* __restrict__ s,
                                  __half* __restrict__ h, int n4) {
    int i = blockIdx.x * blockDim.x + threadIdx.x;
    if (i >= n4) return;
    float4 v = ((const float4*)s)[i];
    ((__half2*)h)[2 * i]     = __floats2half2_rn(v.x, v.y);
    ((__half2*)h)[2 * i + 1] = __floats2half2_rn(v.z, v.w);
}

__global__ void split_half2_kernel(const float* __restrict__ s,
                                   __half* __restrict__ hi,
                                   __half* __restrict__ lo, int n4) {
    int i = blockIdx.x * blockDim.x + threadIdx.x;
    if (i >= n4) return;
    float4 v = ((const float4*)s)[i];
    __half2 h0 = __floats2half2_rn(v.x, v.y);
    __half2 h1 = __floats2half2_rn(v.z, v.w);
    __half2 l0 = __floats2half2_rn(v.x - __half2float(__low2half(h0)),
                                   v.y - __half2float(__high2half(h0)));
    __half2 l1 = __floats2half2_rn(v.z - __half2float(__low2half(h1)),
                                   v.w - __half2float(__high2half(h1)));
    ((__half2*)hi)[2 * i] = h0; ((__half2*)hi)[2 * i + 1] = h1;
    ((__half2*)lo)[2 * i] = l0; ((__half2*)lo)[2 * i + 1] = l1;
}

// ---------------- embed gather + relu ----------------
__global__ void embed_relu_kernel(const int* __restrict__ words,
                                  const float* __restrict__ embed) {
    int row = blockIdx.x;
    int b = row >> 6, t = row & 63;
    int w = words[b * T1c + t];
    const float* e = embed + (long long)w * Ec;
    float* x = g_x + (long long)row * Ec;
    for (int i = threadIdx.x; i < Ec; i += blockDim.x)
        x[i] = fmaxf(e[i], 0.f);
}

// ---------------- h0 (transposed) ----------------
__global__ void h0t_kernel(const float* __restrict__ ehid, int layer) {
    int i = blockIdx.x * blockDim.x + threadIdx.x;
    if (i < Bc * Hc) {
        int b = i >> 9, j = i & 511;
        g_hta[j * Bc + b] = ehid[layer * Bc * Hc + i] + ehid[(layer + 2) * Bc * Hc + i];
    }
}

// ------------- encoder transpose [b][s][d] -> [b][d][s] planes -------------
__global__ void transpose_enc(const float* __restrict__ enc) {
    __shared__ float t[32][33];
    int b = blockIdx.z;
    int d0 = blockIdx.x * 32, s0 = blockIdx.y * 32;
    int tx = threadIdx.x, ty = threadIdx.y;
#pragma unroll
    for (int i = 0; i < 4; i++)
        t[ty + 8 * i][tx] =
            enc[((long long)b * Sc + s0 + ty + 8 * i) * (2 * Hc) + d0 + tx];
    __syncthreads();
#pragma unroll
    for (int i = 0; i < 4; i++) {
        float v = t[tx][ty + 8 * i];
        long long idx = ((long long)b * (2 * Hc) + d0 + ty + 8 * i) * Sc + s0 + tx;
        __nv_bfloat16 h, l; splits(v, h, l);
        g_encT_hi[idx] = h; g_encT_lo[idx] = l;
    }
}

// ---------------- fp32 SIMT GEMM (gi): C = A @ W^T + bias ----------------
__global__ void __launch_bounds__(256)
simt_gemm(const float* __restrict__ A, const float* __restrict__ W,
          const float* __restrict__ bias, float* __restrict__ C,
          int M, int N, int K) {
    __shared__ float As[16 * 68];
    __shared__ float Bs[16 * 68];
    int tid = threadIdx.x;
    int tx = tid & 15, ty = tid >> 4;
    int m0 = blockIdx.y * 64, n0 = blockIdx.x * 64;
    float c[4][4] = {};
    int kt_count = (K + 15) / 16;
    for (int kt = 0; kt < kt_count; kt++) {
        int k0 = kt * 16;
        __syncthreads();
#pragma unroll
        for (int e = tid; e < 1024; e += 256) {
            int r = e >> 4, k = e & 15;
            As[k * 68 + r] = (k0 + k < K) ? A[(long long)(m0 + r) * K + k0 + k] : 0.f;
            Bs[k * 68 + r] = (k0 + k < K) ? W[(long long)(n0 + r) * K + k0 + k] : 0.f;
        }
        __syncthreads();
#pragma unroll
        for (int k = 0; k < 16; k++) {
            float4 a = *(const float4*)&As[k * 68 + ty * 4];
            float4 b = *(const float4*)&Bs[k * 68 + tx * 4];
            float av[4] = {a.x, a.y, a.z, a.w};
            float bv[4] = {b.x, b.y, b.z, b.w};
#pragma unroll
            for (int i = 0; i < 4; i++)
#pragma unroll
                for (int j = 0; j < 4; j++)
                    c[i][j] += av[i] * bv[j];
        }
    }
#pragma unroll
    for (int i = 0; i < 4; i++)
#pragma unroll
        for (int j = 0; j < 4; j++) {
            int row = m0 + ty * 4 + i, col = n0 + tx * 4 + j;
            C[(long long)row * N + col] = c[i][j] + bias[col];
        }
}

// ---------------- persistent GRU layer (software grid barrier) ----------------
// 128 CTAs (one wave), weights staged in smem once; h double-buffered in L2.
__global__ void __launch_bounds__(256, 1)
gru_layer_kernel(const float* __restrict__ Whh, const float* __restrict__ bhh,
                 int layer) {
    __shared__ float ws[6144];          // [gate][jl][k]
    __shared__ float sp[3][4][32];
    int tid = threadIdx.x, bid = blockIdx.x;
    int b = tid & 31, jl = (tid >> 5) & 3, kh = tid >> 7;
    int j = bid * 4 + jl;

    for (int i = tid; i < 6144; i += 256) {
        int g = i >> 11, r = (i >> 9) & 3, k = i & 511;
        ws[i] = Whh[(long long)(g * Hc + bid * 4 + r) * Hc + k];
    }
    float br = bhh[j], bz = bhh[j + Hc], bn = bhh[j + 2 * Hc];
    __syncthreads();
    const float* wr = &ws[jl * 512];
    const float* wz = &ws[2048 + jl * 512];
    const float* wn = &ws[4096 + jl * 512];

    for (int t = 0; t < Tc; t++) {
        const float* hin = (t & 1) ? g_htb : g_hta;
        float* hout      = (t & 1) ? g_hta : g_htb;
        float ar = 0.f, az = 0.f, an = 0.f;
        int k0 = kh * 256;
#pragma unroll 4
        for (int k = k0; k < k0 + 256; k += 4) {
            float4 r4 = *(const float4*)(wr + k);
            float4 z4 = *(const float4*)(wz + k);
            float4 n4 = *(const float4*)(wn + k);
            float h0v = __ldcg(hin + (k + 0) * Bc + b);
            float h1v = __ldcg(hin + (k + 1) * Bc + b);
            float h2v = __ldcg(hin + (k + 2) * Bc + b);
            float h3v = __ldcg(hin + (k + 3) * Bc + b);
            ar += r4.x * h0v + r4.y * h1v + r4.z * h2v + r4.w * h3v;
            az += z4.x * h0v + z4.y * h1v + z4.z * h2v + z4.w * h3v;
            an += n4.x * h0v + n4.y * h1v + n4.z * h2v + n4.w * h3v;
        }
        if (kh) { sp[0][jl][b] = ar; sp[1][jl][b] = az; sp[2][jl][b] = an; }
        __syncthreads();
        if (!kh) {
            ar += sp[0][jl][b]; az += sp[1][jl][b]; an += sp[2][jl][b];
            int row = b * Tc + t;
            const float* g = g_gi + (long long)row * H3c;
            float r = 1.f / (1.f + expf(-(g[j] + ar + br)));
            float z = 1.f / (1.f + expf(-(g[j + Hc] + az + bz)));
            float n = tanhf(g[j + 2 * Hc] + r * (an + bn));
            float hold = __ldcg(hin + j * Bc + b);
            float hnew = (1.f - z) * n + z * hold;
            __stcg(hout + j * Bc + b, hnew);
            if (layer == 0) {
                g_hseq0[(long long)row * Hc + j] = hnew;
            } else {
                __nv_bfloat16 h, l; splits(hnew, h, l);
                g_cat_hi[(long long)row * H3c + j] = h;
                g_cat_lo[(long long)row * H3c + j] = l;
            }
        }
        // software grid barrier
        __syncthreads();
        __threadfence();
        if (tid == 0) {
            atomicAdd(&g_bar_ctr, 1);
            int target = (t + 1) * (int)gridDim.x;
            while (atomicAdd(&g_bar_ctr, 0) < target) {}
        }
        __syncthreads();
    }
    if (tid == 0 && bid == 0) g_bar_ctr = 0;   // reset for next launch / replay
}

// ---------------- softmax (256 wide) -> attn planes ----------------
__global__ void softmax_kernel() {
    int row = blockIdx.x, tid = threadIdx.x;
    __shared__ float sm_[8], ss_[8];
    float v = g_scores[(long long)row * Sc + tid];
    float m = v;
#pragma unroll
    for (int o = 16; o; o >>= 1) m = fmaxf(m, __shfl_xor_sync(~0u, m, o));
    if ((tid & 31) == 0) sm_[tid >> 5] = m;
    __syncthreads();
    float mm = sm_[0];
#pragma unroll
    for (int i = 1; i < 8; i++) mm = fmaxf(mm, sm_[i]);
    float e = expf(v - mm);
    float s = e;
#pragma unroll
    for (int o = 16; o; o >>= 1) s += __shfl_xor_sync(~0u, s, o);
    if ((tid & 31) == 0) ss_[tid >> 5] = s;
    __syncthreads();
    float tot = 0.f;
#pragma unroll
    for (int i = 0; i < 8; i++) tot += ss_[i];
    float p = e / tot;
    __nv_bfloat16 h, l; splits(p, h, l);
    g_attn_hi[(long long)row * Sc + tid] = h;
    g_attn_lo[(long long)row * Sc + tid] = l;
}

// ======================= bf16x3 pipelined tensor GEMM =======================
// OUT: 0 = fp32 C (+bias), 1 = bf16 hi/lo planes, 2 = single fp16 plane (Chi_).
constexpr int GSTAGE = 32768;
constexpr int GSMEM  = 3 * GSTAGE;

template <bool RELU, int OUT>
__global__ void __launch_bounds__(256, 1)
bfx3_gemm(const __nv_bfloat16* __restrict__ Ahi, const __nv_bfloat16* __restrict__ Alo,
          const __nv_bfloat16* __restrict__ Bhi, const __nv_bfloat16* __restrict__ Blo,
          const float* __restrict__ bias, float* __restrict__ C,
          void* __restrict__ Chi_, void* __restrict__ Clo_,
          int M, int N, int K, int lda, int ldc,
          long long sA, long long sB, long long sC) {
    extern __shared__ char smem[];
    uint32_t su = (uint32_t)__cvta_generic_to_shared(smem);

    Ahi += (long long)blockIdx.z * sA;  Alo += (long long)blockIdx.z * sA;
    Bhi += (long long)blockIdx.z * sB;  Blo += (long long)blockIdx.z * sB;

    const int m0 = blockIdx.x * 128, n0 = blockIdx.y * 128;
    const int tid = threadIdx.x;
    const int lane = tid & 31, wid = tid >> 5;
    const int wm = wid & 1, wn = wid >> 1;
    const int lr = lane >> 2, lc = lane & 3;

    float c[4][4][4] = {};

    auto issue_load = [&](int stage, int kt) {
        int kb = kt * 32;
        uint32_t sb = su + stage * GSTAGE;
#pragma unroll
        for (int i = 0; i < 8; i++) {
            int chunkid = tid + 256 * i;
            int plane = chunkid >> 9;
            int w = chunkid & 511;
            int r = w >> 2, cck = w & 3;
            uint32_t dst = sb + plane * 8192 + r * 64 + ((cck ^ ((r >> 1) & 3)) << 4);
            const __nv_bfloat16* src;
            bool ok = true;
            if (plane < 2) {
                int gm = m0 + r;
                src = (plane == 0 ? Ahi : Alo) + (long long)gm * lda + kb + cck * 8;
                ok = gm < M;
            } else {
                int gn = n0 + r;
                src = (plane == 2 ? Bhi : Blo) + (long long)gn * K + kb + cck * 8;
            }
            cpa16(dst, src, ok);
        }
    };

    const int kt_count = K >> 5;
    issue_load(0, 0); cp_commit();
    issue_load(1, 1); cp_commit();

    for (int kt = 0; kt < kt_count; kt++) {
        if (kt + 2 < kt_count) cp_wait1(); else cp_wait0();
        __syncthreads();
        if (kt + 2 < kt_count) { issue_load((kt + 2) % 3, kt + 2); cp_commit(); }

        uint32_t sb = su + (kt % 3) * GSTAGE;
#pragma unroll
        for (int ks = 0; ks < 2; ks++) {
            uint32_t ah[4][4], al[4][4], bh[2][4], bl[2][4];
#pragma unroll
            for (int mi = 0; mi < 4; mi++) {
                int row = wm * 64 + mi * 16 + (lane & 15);
                int ch = 2 * ks + (lane >> 4);
                uint32_t a = sb + row * 64 + ((ch ^ ((row >> 1) & 3)) << 4);
                LDSM4(ah[mi], a);
                LDSM4(al[mi], a + 8192);
            }
#pragma unroll
            for (int np = 0; np < 2; np++) {
                int row = wn * 32 + np * 16 + ((lane >> 4) << 3) + (lane & 7);
                int ch = 2 * ks + ((lane >> 3) & 1);
                uint32_t a = sb + 16384 + row * 64 + ((ch ^ ((row >> 1) & 3)) << 4);
                LDSM4(bh[np], a);
                LDSM4(bl[np], a + 8192);
            }
#pragma unroll
            for (int mi = 0; mi < 4; mi++)
#pragma unroll
                for (int ni = 0; ni < 4; ni++)
                    mma16(c[mi][ni], ah[mi], &bh[ni >> 1][(ni & 1) * 2]);
#pragma unroll
            for (int mi = 0; mi < 4; mi++)
#pragma unroll
                for (int ni = 0; ni < 4; ni++)
                    mma16(c[mi][ni], ah[mi], &bl[ni >> 1][(ni & 1) * 2]);
#pragma unroll
            for (int mi = 0; mi < 4; mi++)
#pragma unroll
                for (int ni = 0; ni < 4; ni++)
                    mma16(c[mi][ni], al[mi], &bh[ni >> 1][(ni & 1) * 2]);
        }
        __syncthreads();
    }

#pragma unroll
    for (int mi = 0; mi < 4; mi++) {
#pragma unroll
        for (int ni = 0; ni < 4; ni++) {
            int row = m0 + wm * 64 + mi * 16 + lr;
            int col = n0 + wn * 32 + ni * 8 + lc * 2;
            float b0 = bias ? bias[col] : 0.f;
            float b1 = bias ? bias[col + 1] : 0.f;
            float v0 = c[mi][ni][0] + b0, v1 = c[mi][ni][1] + b1;
            float v2 = c[mi][ni][2] + b0, v3 = c[mi][ni][3] + b1;
            if (RELU) {
                v0 = fmaxf(v0, 0.f); v1 = fmaxf(v1, 0.f);
                v2 = fmaxf(v2, 0.f); v3 = fmaxf(v3, 0.f);
            }
            if (OUT == 0) {
                float* Cz = C + (long long)blockIdx.z * sC;
                if (row < M)
                    *(float2*)(Cz + (long long)row * ldc + col) = make_float2(v0, v1);
                if (row + 8 < M)
                    *(float2*)(Cz + (long long)(row + 8) * ldc + col) = make_float2(v2, v3);
            } else if (OUT == 1) {
                __nv_bfloat16* Chi = (__nv_bfloat16*)Chi_ + (long long)blockIdx.z * sC;
                __nv_bfloat16* Clo = (__nv_bfloat16*)Clo_ + (long long)blockIdx.z * sC;
                if (row < M) {
                    __nv_bfloat162 h = __floats2bfloat162_rn(v0, v1);
                    __nv_bfloat162 l = __floats2bfloat162_rn(
                        v0 - __bfloat162float(__low2bfloat16(h)),
                        v1 - __bfloat162float(__high2bfloat16(h)));
                    *(__nv_bfloat162*)(Chi + (long long)row * ldc + col) = h;
                    *(__nv_bfloat162*)(Clo + (long long)row * ldc + col) = l;
                }
                if (row + 8 < M) {
                    __nv_bfloat162 h = __floats2bfloat162_rn(v2, v3);
                    __nv_bfloat162 l = __floats2bfloat162_rn(
                        v2 - __bfloat162float(__low2bfloat16(h)),
                        v3 - __bfloat162float(__high2bfloat16(h)));
                    *(__nv_bfloat162*)(Chi + (long long)(row + 8) * ldc + col) = h;
                    *(__nv_bfloat162*)(Clo + (long long)(row + 8) * ldc + col) = l;
                }
            } else {
                __half* Co = (__half*)Chi_;
                if (row < M)
                    *(__half2*)(Co + (long long)row * ldc + col) = __floats2half2_rn(v0, v1);
                if (row + 8 < M)
                    *(__half2*)(Co + (long long)(row + 8) * ldc + col) = __floats2half2_rn(v2, v3);
            }
        }
    }
}

// ============ fp16 pipelined GEMM: C = (sum A-terms) @ Bf^T + bias ============
// AT = number of A fp16 planes (1 or 2); B single fp16.
// OUT: 0 = fp32 C + bias; 1 = bf16 hi/lo planes (+bias).
// M%128==0, N%128==0, K%32==0.
constexpr int FPL = 8192;

template <int AT, int OUT>
__global__ void __launch_bounds__(256, (AT == 1 ? 2 : 1))
fph_gemm(const __half* __restrict__ Ahi, const __half* __restrict__ Alo,
         const __half* __restrict__ Bf, const float* __restrict__ bias,
         float* __restrict__ C,
         __nv_bfloat16* __restrict__ Chi, __nv_bfloat16* __restrict__ Clo,
         int M, int N, int K, int lda, int ldc) {
    extern __shared__ char smem[];
    uint32_t su = (uint32_t)__cvta_generic_to_shared(smem);
    constexpr int NPL = AT + 1;
    constexpr int STG = NPL * FPL;

    const int m0 = blockIdx.x * 128, n0 = blockIdx.y * 128;
    const int tid = threadIdx.x;
    const int lane = tid & 31, wid = tid >> 5;
    const int wm = wid & 1, wn = wid >> 1;
    const int lr = lane >> 2, lc = lane & 3;

    float c[4][4][4] = {};

    auto issue_load = [&](int stage, int kt) {
        int kb = kt * 32;
        uint32_t sb = su + stage * STG;
#pragma unroll
        for (int i = 0; i < NPL * 2; i++) {
            int chunkid = tid + 256 * i;
            int plane = chunkid >> 9;
            int w = chunkid & 511;
            int r = w >> 2, cck = w & 3;
            uint32_t dst = sb + plane * FPL + r * 64 + ((cck ^ ((r >> 1) & 3)) << 4);
            const __half* src;
            if (plane < AT)
                src = (plane == 0 ? Ahi : Alo) + (long long)(m0 + r) * lda + kb + cck * 8;
            else
                src = Bf + (long long)(n0 + r) * K + kb + cck * 8;
            cpa16u(dst, src);
        }
    };

    const int kt_count = K >> 5;
    issue_load(0, 0); cp_commit();
    issue_load(1, 1); cp_commit();

    for (int kt = 0; kt < kt_count; kt++) {
        if (kt + 2 < kt_count) cp_wait1(); else cp_wait0();
        __syncthreads();
        if (kt + 2 < kt_count) { issue_load((kt + 2) % 3, kt + 2); cp_commit(); }

        uint32_t sb = su + (kt % 3) * STG;
#pragma unroll
        for (int ks = 0; ks < 2; ks++) {
            uint32_t ah[AT][4][4], bh[2][4];
#pragma unroll
            for (int t = 0; t < AT; t++)
#pragma unroll
                for (int mi = 0; mi < 4; mi++) {
                    int row = wm * 64 + mi * 16 + (lane & 15);
                    int ch = 2 * ks + (lane >> 4);
                    uint32_t a = sb + t * FPL + row * 64 + ((ch ^ ((row >> 1) & 3)) << 4);
                    LDSM4(ah[t][mi], a);
                }
#pragma unroll
            for (int np = 0; np < 2; np++) {
                int row = wn * 32 + np * 16 + ((lane >> 4) << 3) + (lane & 7);
                int ch = 2 * ks + ((lane >> 3) & 1);
                uint32_t a = sb + AT * FPL + row * 64 + ((ch ^ ((row >> 1) & 3)) << 4);
                LDSM4(bh[np], a);
            }
#pragma unroll
            for (int t = 0; t < AT; t++)
#pragma unroll
                for (int mi = 0; mi < 4; mi++)
#pragma unroll
                    for (int ni = 0; ni < 4; ni++)
                        mma16h(c[mi][ni], ah[t][mi], &bh[ni >> 1][(ni & 1) * 2]);
        }
        __syncthreads();
    }

#pragma unroll
    for (int mi = 0; mi < 4; mi++) {
#pragma unroll
        for (int ni = 0; ni < 4; ni++) {
            int row = m0 + wm * 64 + mi * 16 + lr;
            int col = n0 + wn * 32 + ni * 8 + lc * 2;
            float b0 = bias ? bias[col] : 0.f;
            float b1 = bias ? bias[col + 1] : 0.f;
            float v0 = c[mi][ni][0] + b0, v1 = c[mi][ni][1] + b1;
            float v2 = c[mi][ni][2] + b0, v3 = c[mi][ni][3] + b1;
            if (OUT == 0) {
                *(float2*)(C + (long long)row * ldc + col) = make_float2(v0, v1);
                *(float2*)(C + (long long)(row + 8) * ldc + col) = make_float2(v2, v3);
            } else {
                __nv_bfloat162 h = __floats2bfloat162_rn(v0, v1);
                __nv_bfloat162 l = __floats2bfloat162_rn(
                    v0 - __bfloat162float(__low2bfloat16(h)),
                    v1 - __bfloat162float(__high2bfloat16(h)));
                *(__nv_bfloat162*)(Chi + (long long)row * ldc + col) = h;
                *(__nv_bfloat162*)(Clo + (long long)row * ldc + col) = l;
                h = __floats2bfloat162_rn(v2, v3);
                l = __floats2bfloat162_rn(v2 - __bfloat162float(__low2bfloat16(h)),
                                          v3 - __bfloat162float(__high2bfloat16(h)));
                *(__nv_bfloat162*)(Chi + (long long)(row + 8) * ldc + col) = h;
                *(__nv_bfloat162*)(Clo + (long long)(row + 8) * ldc + col) = l;
            }
        }
    }
}

// ---------------- host launch ----------------
extern "C" void kernel_launch(void* const* d_in, const int* in_sizes, int n_in,
                              void* d_out, int out_size) {
    (void)in_sizes; (void)n_in; (void)out_size;
    const float* enc    = (const float*)d_in[0];
    const float* ehid   = (const float*)d_in[1];
    const int*   words  = (const int*)d_in[2];
    const float* embed  = (const float*)d_in[3];
    const float* Wih0   = (const float*)d_in[4];
    const float* Whh0   = (const float*)d_in[5];
    const float* bih0   = (const float*)d_in[6];
    const float* bhh0   = (const float*)d_in[7];
    const float* Wih1   = (const float*)d_in[8];
    const float* Whh1   = (const float*)d_in[9];
    const float* bih1   = (const float*)d_in[10];
    const float* bhh1   = (const float*)d_in[11];
    const float* attn_W = (const float*)d_in[12];
    const float* attn_b = (const float*)d_in[13];
    const float* aw_W   = (const float*)d_in[14];
    const float* aw_b   = (const float*)d_in[15];
    const float* out_W  = (const float*)d_in[16];
    const float* out_b  = (const float*)d_in[17];
    float* out = (float*)d_out;

    float *p_x, *p_gi, *p_h0, *p_sc;
    cudaGetSymbolAddress((void**)&p_x,  g_x);
    cudaGetSymbolAddress((void**)&p_gi, g_gi);
    cudaGetSymbolAddress((void**)&p_h0, g_hseq0);
    cudaGetSymbolAddress((void**)&p_sc, g_scores);

#define GETP(sym) \
    __nv_bfloat16 *sym##_h, *sym##_l; \
    cudaGetSymbolAddress((void**)&sym##_h, sym##_hi); \
    cudaGetSymbolAddress((void**)&sym##_l, sym##_lo);
    GETP(g_proj) GETP(g_encT) GETP(g_attn) GETP(g_cat) GETP(g_awW)
#undef GETP
    __half *p_encfh, *p_encfl, *p_awf, *p_of, *p_wf;
    cudaGetSymbolAddress((void**)&p_encfh, g_enc_fh);
    cudaGetSymbolAddress((void**)&p_encfl, g_enc_fl);
    cudaGetSymbolAddress((void**)&p_awf,   g_attnW_f);
    cudaGetSymbolAddress((void**)&p_of,    g_o_f);
    cudaGetSymbolAddress((void**)&p_wf,    g_outW_f);

    cudaFuncSetAttribute(bfx3_gemm<false, 0>,
                         cudaFuncAttributeMaxDynamicSharedMemorySize, GSMEM);
    cudaFuncSetAttribute(bfx3_gemm<false, 1>,
                         cudaFuncAttributeMaxDynamicSharedMemorySize, GSMEM);
    cudaFuncSetAttribute(bfx3_gemm<true, 2>,
                         cudaFuncAttributeMaxDynamicSharedMemorySize, GSMEM);
    cudaFuncSetAttribute(fph_gemm<1, 0>,
                         cudaFuncAttributeMaxDynamicSharedMemorySize, 3 * 2 * FPL);
    cudaFuncSetAttribute(fph_gemm<2, 1>,
                         cudaFuncAttributeMaxDynamicSharedMemorySize, 3 * 3 * FPL);

    // ---- one-time operand conversions ----
    {
        int n4 = Bc * Sc * 2 * Hc / 4;
        split_half2_kernel<<<(n4 + 255) / 256, 256>>>(enc, p_encfh, p_encfl, n4);
        n4 = Hc * 2 * Hc / 4;
        split_half_kernel<<<(n4 + 255) / 256, 256>>>(attn_W, p_awf, n4);
        n4 = H3c * H3c / 4;
        split_kernel<<<(n4 + 255) / 256, 256>>>(aw_W, g_awW_h, g_awW_l, n4);
        n4 = Vc * H3c / 4;
        split_half_kernel<<<(n4 + 255) / 256, 256>>>(out_W, p_wf, n4);
    }
    transpose_enc<<<dim3(32, 8, 32), dim3(32, 8)>>>(enc);
    embed_relu_kernel<<<ROWS, 128>>>(words, embed);

    // proj = enc @ attn_W^T + attn_b  (M=8192 N=512 K=1024) -> bf16 planes
    fph_gemm<2, 1><<<dim3(64, 4), 256, 3 * 3 * FPL>>>(
        p_encfh, p_encfl, p_awf, attn_b, nullptr, g_proj_h, g_proj_l,
        Bc * Sc, Hc, 2 * Hc, 2 * Hc, Hc);

    // ---- layer 0 ----
    h0t_kernel<<<64, 256>>>(ehid, 0);
    simt_gemm<<<dim3(H3c / 64, ROWS / 64), 256>>>(p_x, Wih0, bih0, p_gi,
                                                  ROWS, H3c, Ec);
    gru_layer_kernel<<<128, 256>>>(Whh0, bhh0, 0);

    // ---- layer 1 ----
    h0t_kernel<<<64, 256>>>(ehid, 1);
    simt_gemm<<<dim3(H3c / 64, ROWS / 64), 256>>>(p_h0, Wih1, bih1, p_gi,
                                                  ROWS, H3c, Hc);
    gru_layer_kernel<<<128, 256>>>(Whh1, bhh1, 1);

    // scores[b] = h[b] @ proj[b]^T  (M=64 N=256 K=512, batch 32) -> fp32
    bfx3_gemm<false, 0><<<dim3(1, 2, 32), 256, GSMEM>>>(
        g_cat_h, g_cat_l, g_proj_h, g_proj_l, nullptr,
        p_sc, nullptr, nullptr,
        Tc, Sc, Hc, H3c, Sc,
        (long long)Tc * H3c, (long long)Sc * Hc, (long long)Tc * Sc);
    softmax_kernel<<<ROWS, 256>>>();
    // ctx[b] = attn[b] @ encT[b]^T  (M=64 N=1024 K=256) -> cat planes cols 512+
    bfx3_gemm<false, 1><<<dim3(1, 8, 32), 256, GSMEM>>>(
        g_attn_h, g_attn_l, g_encT_h, g_encT_l, nullptr,
        nullptr, g_cat_h + Hc, g_cat_l + Hc,
        Tc, 2 * Hc, Sc, Sc, H3c,
        (long long)Tc * Sc, (long long)2 * Hc * Sc, (long long)Tc * H3c);

    // o = relu(cat @ aw_W^T + aw_b)  (M=2048 N=1536 K=1536) -> single fp16
    bfx3_gemm<true, 2><<<dim3(16, 12, 1), 256, GSMEM>>>(
        g_cat_h, g_cat_l, g_awW_h, g_awW_l, aw_b,
        nullptr, p_of, nullptr,
        ROWS, H3c, H3c, H3c, H3c, 0, 0, 0);

    // logits = o @ out_W^T + out_b  (M=2048 N=32000 K=1536) -> fp32 out
    fph_gemm<1, 0><<<dim3(16, 250), 256, 3 * 2 * FPL>>>(
        p_of, nullptr, p_wf, out_b, out, nullptr, nullptr,
        ROWS, Vc, H3c, H3c, Vc);
}